// round 12
// baseline (speedup 1.0000x reference)
#include <cuda_runtime.h>
#include <cuda_bf16.h>
#include <cstdint>

#define NNODES 50000
#define NEDGES 800000
#define NF     128
#define EF     32
#define HID    300
#define MSGD   128
#define NHID   128
#define NGRAPH 64

#define ECHUNK 200000
#define NCHUNK (NEDGES / ECHUNK)
#define KP     320      // padded K for HID=300 activations

typedef unsigned long long u64;

// ---------------------------------------------------------------------------
// Scratch (__device__ globals; total ~950MB, < 2GB for GOTPCREL safety)
// ---------------------------------------------------------------------------
__device__ float g_Pa[NNODES * HID];
__device__ float g_Pb[NNODES * HID];
__device__ float g_aggr[NNODES * MSGD];
__device__ float g_hn[NNODES * NHID];
__device__ float g_pool[NGRAPH * NHID];
__device__ float g_cnt[NGRAPH];
__device__ int   g_src[NEDGES];
__device__ int   g_dst[NEDGES];
__device__ int   g_batch[NNODES];
__device__ int   g_e64;
__device__ int   g_b64;

// pre-split activations (bf16 hi/lo, row-major [M][Kpad])
__device__ __nv_bfloat16 g_xH[NNODES * NF],     g_xL[NNODES * NF];
__device__ __nv_bfloat16 g_h1H[(size_t)ECHUNK * KP], g_h1L[(size_t)ECHUNK * KP];
__device__ __nv_bfloat16 g_h2H[(size_t)ECHUNK * KP], g_h2L[(size_t)ECHUNK * KP];
__device__ __nv_bfloat16 g_uH[NNODES * 256],    g_uL[NNODES * 256];
__device__ __nv_bfloat16 g_a1H[NNODES * KP],    g_a1L[NNODES * KP];
__device__ __nv_bfloat16 g_a2H[NNODES * KP],    g_a2L[NNODES * KP];

// split-transposed weights: Wt[n][kpad] bf16 hi/lo
__device__ __nv_bfloat16 g_wpaH[300*128], g_wpaL[300*128];
__device__ __nv_bfloat16 g_wpbH[300*128], g_wpbL[300*128];
__device__ __nv_bfloat16 g_w2H [300*320], g_w2L [300*320];
__device__ __nv_bfloat16 g_w3H [128*320], g_w3L [128*320];
__device__ __nv_bfloat16 g_wn1H[300*256], g_wn1L[300*256];
__device__ __nv_bfloat16 g_wn2H[300*320], g_wn2L[300*320];
__device__ __nv_bfloat16 g_wn3H[128*320], g_wn3L[128*320];

// ---------------------------------------------------------------------------
// helpers
// ---------------------------------------------------------------------------
__device__ __forceinline__ uint32_t smem_u32(const void* p) {
    uint32_t a;
    asm("{ .reg .u64 t; cvta.to.shared.u64 t, %1; cvt.u32.u64 %0, t; }"
        : "=r"(a) : "l"(p));
    return a;
}
__device__ __forceinline__ void ldm_x4(uint32_t* r, uint32_t addr) {
    asm volatile("ldmatrix.sync.aligned.m8n8.x4.shared.b16 {%0,%1,%2,%3}, [%4];"
        : "=r"(r[0]), "=r"(r[1]), "=r"(r[2]), "=r"(r[3]) : "r"(addr));
}
__device__ __forceinline__ void mma16816(float* c, const uint32_t* a,
                                         const uint32_t* b) {
    asm volatile(
        "mma.sync.aligned.m16n8k16.row.col.f32.bf16.bf16.f32 "
        "{%0,%1,%2,%3}, {%4,%5,%6,%7}, {%8,%9}, {%0,%1,%2,%3};"
        : "+f"(c[0]), "+f"(c[1]), "+f"(c[2]), "+f"(c[3])
        : "r"(a[0]), "r"(a[1]), "r"(a[2]), "r"(a[3]), "r"(b[0]), "r"(b[1]));
}
// split two floats into packed hi/lo bf16x2 words
__device__ __forceinline__ void split2(float v0, float v1,
                                       uint32_t& hw, uint32_t& lw) {
    __nv_bfloat16 h0 = __float2bfloat16(v0), h1 = __float2bfloat16(v1);
    __nv_bfloat16 l0 = __float2bfloat16(v0 - __bfloat162float(h0));
    __nv_bfloat16 l1 = __float2bfloat16(v1 - __bfloat162float(h1));
    hw = (uint32_t)__bfloat16_as_ushort(h0) | ((uint32_t)__bfloat16_as_ushort(h1) << 16);
    lw = (uint32_t)__bfloat16_as_ushort(l0) | ((uint32_t)__bfloat16_as_ushort(l1) << 16);
}

// ---------------------------------------------------------------------------
// small kernels
// ---------------------------------------------------------------------------
__global__ void detect_k(const int* __restrict__ e, const int* __restrict__ b, int nn) {
    __shared__ int se, sb;
    int t = threadIdx.x;
    if (t == 0) { se = 1; sb = 1; }
    __syncthreads();
    if (e[2 * t + 1] != 0) se = 0;
    int w = nn - 1 - 2 * t;
    if (b[w] != 0) sb = 0;
    __syncthreads();
    if (t == 0) { g_e64 = se; g_b64 = sb; }
}
__global__ void convert_k(const int* __restrict__ e, const int* __restrict__ b,
                          int ne, int nn) {
    int i = blockIdx.x * blockDim.x + threadIdx.x;
    int e64 = g_e64, b64 = g_b64;
    if (i < ne) {
        if (e64) { g_src[i] = e[2 * i]; g_dst[i] = e[2 * (ne + i)]; }
        else     { g_src[i] = e[i];     g_dst[i] = e[ne + i]; }
    }
    if (i < nn) g_batch[i] = b64 ? b[2 * i] : b[i];
}
__global__ void zero_k() {
    long i = blockIdx.x * (long)blockDim.x + threadIdx.x;
    long stride = gridDim.x * (long)blockDim.x;
    for (long j = i; j < (long)NNODES * MSGD; j += stride) g_aggr[j] = 0.0f;
    if (i < NGRAPH * NHID) g_pool[i] = 0.0f;
    if (i < NGRAPH) g_cnt[i] = 0.0f;
}
// zero pad columns [300,320) of padded activation buffers
__global__ void padzero_k() {
    long i = blockIdx.x * (long)blockDim.x + threadIdx.x;
    long stride = gridDim.x * (long)blockDim.x;
    const long ne = (long)ECHUNK * 20, nn = (long)NNODES * 20;
    for (long j = i; j < ne; j += stride) {
        long r = j / 20; int c = 300 + (int)(j % 20);
        g_h1H[r * KP + c] = __nv_bfloat16(0.f); g_h1L[r * KP + c] = __nv_bfloat16(0.f);
        g_h2H[r * KP + c] = __nv_bfloat16(0.f); g_h2L[r * KP + c] = __nv_bfloat16(0.f);
    }
    for (long j = i; j < nn; j += stride) {
        long r = j / 20; int c = 300 + (int)(j % 20);
        g_a1H[r * KP + c] = __nv_bfloat16(0.f); g_a1L[r * KP + c] = __nv_bfloat16(0.f);
        g_a2H[r * KP + c] = __nv_bfloat16(0.f); g_a2L[r * KP + c] = __nv_bfloat16(0.f);
    }
}
// generic fp32 -> split bf16
__global__ void split_k(const float* __restrict__ src,
                        __nv_bfloat16* __restrict__ H, __nv_bfloat16* __restrict__ L,
                        int n2) {   // n2 = n/2 (pairs)
    int i = blockIdx.x * blockDim.x + threadIdx.x;
    if (i >= n2) return;
    float2 v = ((const float2*)src)[i];
    uint32_t hw, lw;
    split2(v.x, v.y, hw, lw);
    ((uint32_t*)H)[i] = hw;
    ((uint32_t*)L)[i] = lw;
}
// W[K][N] row-major (ld=ldw) -> hi/lo [N][kpad] bf16, zero-padded in k
__global__ void wprep_k(const float* __restrict__ W, int K, int Nw, int ldw,
                        __nv_bfloat16* __restrict__ hi, __nv_bfloat16* __restrict__ lo,
                        int kpad) {
    int idx = blockIdx.x * blockDim.x + threadIdx.x;
    if (idx >= Nw * kpad) return;
    int n = idx / kpad, k = idx % kpad;
    float v = (k < K) ? W[(size_t)k * ldw + n] : 0.0f;
    __nv_bfloat16 h = __float2bfloat16(v);
    hi[idx] = h;
    lo[idx] = __float2bfloat16(v - __bfloat162float(h));
}

// ---------------------------------------------------------------------------
// Tensor GEMM, pre-split operands (zero conversion in the hot loop).
// C = epi(A @ Wt^T); A = AH+AL [M][K] bf16 (K = padded, mult of 32, same
// stride both sides); Wt = BH+BL [N][K].
// 3 products: hi*hi + hi*lo + lo*hi, fp32 accum.
// CTA 128x64, BK=32, 256 thr (8 warps 4m x 2n, warp 32x32).
// Smem rows 80B-padded (conflict-free ldmatrix, no swizzle).
// MODE 0: epi = (relu?)(acc+bias); store fp32 C, or split bf16 OH/OL if set.
// MODE 2: atomicAdd(C[rdst[row]*ldc + col], acc+bias)
// ---------------------------------------------------------------------------
#define RSB 80
#define OF_AH 0
#define OF_AL 10240
#define OF_BH 20480
#define OF_BL 25600
#define TBUF  30720
#define TSMEM (2*TBUF)

template <int MODE>
__global__ void __launch_bounds__(256, 2)
tmma_k(int M, int N, int K,
       const __nv_bfloat16* __restrict__ AH, const __nv_bfloat16* __restrict__ AL,
       const __nv_bfloat16* __restrict__ BH, const __nv_bfloat16* __restrict__ BL,
       const float* __restrict__ bias,
       float* __restrict__ C, int ldc, int relu,
       __nv_bfloat16* __restrict__ OH, __nv_bfloat16* __restrict__ OL, int ldco,
       const int* __restrict__ rdst) {
    extern __shared__ char sm[];
    const uint32_t smb = smem_u32(sm);
    const int tid = threadIdx.x;
    const int lane = tid & 31;
    const int wid = tid >> 5;
    const int wm = wid & 3, wn = wid >> 2;
    const int col0 = blockIdx.x * 64;
    const int row0 = blockIdx.y * 128;

    float cc[2][4][4];
#pragma unroll
    for (int a = 0; a < 2; a++)
#pragma unroll
        for (int b = 0; b < 4; b++)
#pragma unroll
            for (int c = 0; c < 4; c++) cc[a][b][c] = 0.0f;

    uint4 vah[2], val[2];    // A: 16 bf16 hi + 16 lo
    uint4 vbh, vbl;          // B: 8+8 bf16

    const int rowA = tid >> 1, halfA = tid & 1;   // 2 thr/row, 32B halves
    const int nB = tid >> 2, segB = tid & 3;

    auto ldgA = [&](int k0) {
        int grow = row0 + rowA;
        if (grow < M) {
            const uint4* p = (const uint4*)(AH + (size_t)grow * K + k0 + halfA * 16);
            vah[0] = p[0]; vah[1] = p[1];
            const uint4* q = (const uint4*)(AL + (size_t)grow * K + k0 + halfA * 16);
            val[0] = q[0]; val[1] = q[1];
        } else {
            vah[0] = vah[1] = val[0] = val[1] = make_uint4(0, 0, 0, 0);
        }
    };
    auto ldgB = [&](int k0) {
        if (col0 + nB < N) {
            vbh = *(const uint4*)(BH + (size_t)(col0 + nB) * K + k0 + segB * 8);
            vbl = *(const uint4*)(BL + (size_t)(col0 + nB) * K + k0 + segB * 8);
        } else {
            vbh = make_uint4(0, 0, 0, 0);
            vbl = make_uint4(0, 0, 0, 0);
        }
    };
    auto sts = [&](int buf) {
        char* ba = sm + buf + OF_AH + rowA * RSB + halfA * 32;
        *(uint4*)(ba + 0) = vah[0]; *(uint4*)(ba + 16) = vah[1];
        char* bl_ = sm + buf + OF_AL + rowA * RSB + halfA * 32;
        *(uint4*)(bl_ + 0) = val[0]; *(uint4*)(bl_ + 16) = val[1];
        *(uint4*)(sm + buf + OF_BH + nB * RSB + segB * 16) = vbh;
        *(uint4*)(sm + buf + OF_BL + nB * RSB + segB * 16) = vbl;
    };
    auto compute = [&](int buf) {
#pragma unroll
        for (int k16 = 0; k16 < 32; k16 += 16) {
            uint32_t ah[2][4], al[2][4], bh[4][2], bl2[4][2];
#pragma unroll
            for (int mt = 0; mt < 2; mt++) {
                uint32_t ad = smb + buf + OF_AH
                    + (uint32_t)(wm * 32 + mt * 16 + (lane & 15)) * RSB
                    + (uint32_t)(k16 + (lane >> 4) * 8) * 2;
                ldm_x4(ah[mt], ad);
                ldm_x4(al[mt], ad + (OF_AL - OF_AH));
            }
            {
                int g = lane >> 3, r = lane & 7;
#pragma unroll
                for (int np = 0; np < 2; np++) {
                    uint32_t bd = smb + buf + OF_BH
                        + (uint32_t)(wn * 32 + np * 16 + ((g >> 1) & 1) * 8 + r) * RSB
                        + (uint32_t)(k16 + (g & 1) * 8) * 2;
                    uint32_t t4[4];
                    ldm_x4(t4, bd);
                    bh[np * 2][0] = t4[0]; bh[np * 2][1] = t4[1];
                    bh[np * 2 + 1][0] = t4[2]; bh[np * 2 + 1][1] = t4[3];
                    ldm_x4(t4, bd + (OF_BL - OF_BH));
                    bl2[np * 2][0] = t4[0]; bl2[np * 2][1] = t4[1];
                    bl2[np * 2 + 1][0] = t4[2]; bl2[np * 2 + 1][1] = t4[3];
                }
            }
#pragma unroll
            for (int mt = 0; mt < 2; mt++)
#pragma unroll
                for (int nt = 0; nt < 4; nt++) {
                    mma16816(cc[mt][nt], ah[mt], bh[nt]);
                    mma16816(cc[mt][nt], ah[mt], bl2[nt]);
                    mma16816(cc[mt][nt], al[mt], bh[nt]);
                }
        }
    };

    const int nst = K / 32;
    ldgA(0); ldgB(0);
    sts(0);
    __syncthreads();
    for (int s = 0; s < nst; s++) {
        const int buf = (s & 1) * TBUF;
        if (s + 1 < nst) { ldgA((s + 1) * 32); ldgB((s + 1) * 32); }
        compute(buf);
        if (s + 1 < nst) {
            sts(((s + 1) & 1) * TBUF);
            __syncthreads();
        }
    }

#pragma unroll
    for (int mt = 0; mt < 2; mt++) {
#pragma unroll
        for (int h = 0; h < 2; h++) {
            int row = row0 + wm * 32 + mt * 16 + (lane >> 2) + h * 8;
            if (row >= M) continue;
            int dn = (MODE == 2) ? rdst[row] : 0;
#pragma unroll
            for (int nt = 0; nt < 4; nt++) {
                int col = col0 + wn * 32 + nt * 8 + (lane & 3) * 2;
                if (col >= N) continue;
                float v0 = cc[mt][nt][h * 2], v1 = cc[mt][nt][h * 2 + 1];
                if (bias) {
                    float2 bb = *(const float2*)(bias + col);
                    v0 += bb.x; v1 += bb.y;
                }
                if (MODE == 0) {
                    if (relu) { v0 = fmaxf(v0, 0.f); v1 = fmaxf(v1, 0.f); }
                    if (OH) {
                        uint32_t hw, lw;
                        split2(v0, v1, hw, lw);
                        *(uint32_t*)(OH + (size_t)row * ldco + col) = hw;
                        *(uint32_t*)(OL + (size_t)row * ldco + col) = lw;
                    } else {
                        *(float2*)(C + (size_t)row * ldc + col) = make_float2(v0, v1);
                    }
                } else {
                    atomicAdd(C + (size_t)dn * ldc + col, v0);
                    atomicAdd(C + (size_t)dn * ldc + col + 1, v1);
                }
            }
        }
    }
}

// ---------------------------------------------------------------------------
// SIMT FFMA2 edge layer-1: h1 = relu(eattr@W1c + Pa[dst] + Pb[src]),
// output written pre-split bf16 hi/lo (ld = KP).
// ---------------------------------------------------------------------------
#define BM 128
#define BN 128
#define BK 16
#define TM 8
#define TN 8
__device__ __forceinline__ u64 ffma2(u64 a, u64 b, u64 c) {
    u64 d;
    asm("fma.rn.f32x2 %0, %1, %2, %3;" : "=l"(d) : "l"(a), "l"(b), "l"(c));
    return d;
}
__device__ __forceinline__ u64 pack2(float lo, float hi) {
    u64 d;
    asm("mov.b64 %0, {%1, %2};" : "=l"(d) : "f"(lo), "f"(hi));
    return d;
}

__global__ void __launch_bounds__(256, 2)
edge1_k(int M, int N, int K,
        const float* __restrict__ A, int lda,
        const float* __restrict__ B, int ldb,
        __nv_bfloat16* __restrict__ OH, __nv_bfloat16* __restrict__ OL, int ldco,
        const int* __restrict__ rdst, const int* __restrict__ rsrc,
        const float* __restrict__ Pa, const float* __restrict__ Pb, int ldp) {
    __shared__ float As[2][BK * BM];
    __shared__ float Bs[2][BK * BN];
    const int row0 = blockIdx.x * BM;
    const int col0 = blockIdx.y * BN;
    const int tid = threadIdx.x;
    const int tr = tid / (BN / TN);
    const int tc = tid % (BN / TN);
    const int aRow = tid / (BK / 4), aCol4 = tid % (BK / 4);
    const int bRow = tid / (BN / 4), bCol4 = tid % (BN / 4);

    u64 acc2[TM / 2][TN];
#pragma unroll
    for (int i = 0; i < TM / 2; i++)
#pragma unroll
        for (int j = 0; j < TN; j++) acc2[i][j] = 0ull;

    float4 va[2], vb[2];
    auto ldg = [&](int k0) {
#pragma unroll
        for (int r = 0; r < 2; r++) {
            int grow = row0 + aRow + r * 64, gk = k0 + aCol4 * 4;
            va[r] = make_float4(0.f, 0.f, 0.f, 0.f);
            if (grow < M && gk < K)
                va[r] = *(const float4*)(A + (size_t)grow * lda + gk);
        }
#pragma unroll
        for (int r = 0; r < 2; r++) {
            int gk = k0 + bRow + r * 8, gcol = col0 + bCol4 * 4;
            vb[r] = make_float4(0.f, 0.f, 0.f, 0.f);
            if (gk < K && gcol < N)
                vb[r] = *(const float4*)(B + (size_t)gk * ldb + gcol);
        }
    };
    auto sts = [&](int buf) {
#pragma unroll
        for (int r = 0; r < 2; r++) {
            As[buf][(aCol4 * 4 + 0) * BM + aRow + r * 64] = va[r].x;
            As[buf][(aCol4 * 4 + 1) * BM + aRow + r * 64] = va[r].y;
            As[buf][(aCol4 * 4 + 2) * BM + aRow + r * 64] = va[r].z;
            As[buf][(aCol4 * 4 + 3) * BM + aRow + r * 64] = va[r].w;
        }
#pragma unroll
        for (int r = 0; r < 2; r++)
            *(float4*)(&Bs[buf][(bRow + r * 8) * BN + bCol4 * 4]) = vb[r];
    };

    const int nst = (K + BK - 1) / BK;
    ldg(0); sts(0);
    __syncthreads();
    for (int s = 0; s < nst; s++) {
        const int buf = s & 1;
        if (s + 1 < nst) ldg((s + 1) * BK);
#pragma unroll
        for (int kk = 0; kk < BK; kk++) {
            ulonglong2 pa0 = *(const ulonglong2*)&As[buf][kk * BM + tr * TM];
            ulonglong2 pa1 = *(const ulonglong2*)&As[buf][kk * BM + tr * TM + 4];
            u64 ra2[TM / 2] = {pa0.x, pa0.y, pa1.x, pa1.y};
            float4 b0 = *(const float4*)&Bs[buf][kk * BN + tc * TN];
            float4 b1 = *(const float4*)&Bs[buf][kk * BN + tc * TN + 4];
            u64 rb2[TN];
            rb2[0] = pack2(b0.x, b0.x); rb2[1] = pack2(b0.y, b0.y);
            rb2[2] = pack2(b0.z, b0.z); rb2[3] = pack2(b0.w, b0.w);
            rb2[4] = pack2(b1.x, b1.x); rb2[5] = pack2(b1.y, b1.y);
            rb2[6] = pack2(b1.z, b1.z); rb2[7] = pack2(b1.w, b1.w);
#pragma unroll
            for (int i = 0; i < TM / 2; i++)
#pragma unroll
                for (int j = 0; j < TN; j++)
                    acc2[i][j] = ffma2(ra2[i], rb2[j], acc2[i][j]);
        }
        if (s + 1 < nst) { sts(buf ^ 1); __syncthreads(); }
    }

#pragma unroll
    for (int i2 = 0; i2 < TM / 2; i2++) {
        float2 f[TN];
#pragma unroll
        for (int j = 0; j < TN; j++) f[j] = *(float2*)&acc2[i2][j];
#pragma unroll
        for (int w = 0; w < 2; w++) {
            int row = row0 + tr * TM + 2 * i2 + w;
            if (row >= M) continue;
            int dn = rdst[row], sn = rsrc[row];
#pragma unroll
            for (int j = 0; j < TN; j += 4) {
                int col = col0 + tc * TN + j;
                if (col >= N) continue;
                float4 v;
                if (w == 0) v = make_float4(f[j].x, f[j+1].x, f[j+2].x, f[j+3].x);
                else        v = make_float4(f[j].y, f[j+1].y, f[j+2].y, f[j+3].y);
                float4 a4 = *(const float4*)(Pa + (size_t)dn * ldp + col);
                float4 b4 = *(const float4*)(Pb + (size_t)sn * ldp + col);
                v.x = fmaxf(v.x + a4.x + b4.x, 0.f);
                v.y = fmaxf(v.y + a4.y + b4.y, 0.f);
                v.z = fmaxf(v.z + a4.z + b4.z, 0.f);
                v.w = fmaxf(v.w + a4.w + b4.w, 0.f);
                uint32_t hw0, lw0, hw1, lw1;
                split2(v.x, v.y, hw0, lw0);
                split2(v.z, v.w, hw1, lw1);
                *(uint2*)(OH + (size_t)row * ldco + col) = make_uint2(hw0, hw1);
                *(uint2*)(OL + (size_t)row * ldco + col) = make_uint2(lw0, lw1);
            }
        }
    }
}

// concat u = [x, aggr] -> split bf16
__global__ void concat_k(const float* __restrict__ x, int nn) {
    int i = blockIdx.x * blockDim.x + threadIdx.x;   // over nn*128 pairs
    if (i >= nn * 128) return;
    int n = i >> 7, c2 = i & 127;                    // pair index within 256
    float v0, v1;
    if (c2 < 64) { v0 = x[n * NF + 2 * c2]; v1 = x[n * NF + 2 * c2 + 1]; }
    else { v0 = g_aggr[n * MSGD + 2 * (c2 - 64)]; v1 = g_aggr[n * MSGD + 2 * (c2 - 64) + 1]; }
    uint32_t hw, lw;
    split2(v0, v1, hw, lw);
    ((uint32_t*)g_uH)[i] = hw;
    ((uint32_t*)g_uL)[i] = lw;
}
__global__ void pool_k(const float* __restrict__ h, int nn) {
    int idx = blockIdx.x * blockDim.x + threadIdx.x;
    int n = idx >> 7, c = idx & 127;
    if (n < nn) {
        int b = g_batch[n];
        atomicAdd(&g_pool[b * NHID + c], h[idx]);
        if (c == 0) atomicAdd(&g_cnt[b], 1.0f);
    }
}
__global__ void gmlp_k(const float* __restrict__ W1, const float* __restrict__ b1,
                       const float* __restrict__ W2, const float* __restrict__ b2,
                       const float* __restrict__ W3, const float* __restrict__ b3,
                       float* __restrict__ out) {
    int g = blockIdx.x, t = threadIdx.x;
    __shared__ float s_in[NHID], s_h[NHID];
    float c = fmaxf(g_cnt[g], 1.0f);
    s_in[t] = g_pool[g * NHID + t] / c;
    __syncthreads();
    float a = b1[t];
    for (int k = 0; k < NHID; k++) a += s_in[k] * W1[k * NHID + t];
    s_h[t] = fmaxf(a, 0.0f);
    __syncthreads();
    a = b2[t];
    for (int k = 0; k < NHID; k++) a += s_h[k] * W2[k * NHID + t];
    a = fmaxf(a, 0.0f);
    __syncthreads();
    s_in[t] = a * W3[t];
    __syncthreads();
    for (int s = 64; s > 0; s >>= 1) {
        if (t < s) s_in[t] += s_in[t + s];
        __syncthreads();
    }
    if (t == 0) out[g] = s_in[0] + b3[0];
}

// ---------------------------------------------------------------------------
// launch
// ---------------------------------------------------------------------------
extern "C" void kernel_launch(void* const* d_in, const int* in_sizes, int n_in,
                              void* d_out, int out_size) {
    const float* x       = (const float*)d_in[0];
    const int*   eidx    = (const int*)d_in[1];
    const float* eattr   = (const float*)d_in[2];
    const int*   batch   = (const int*)d_in[3];
    const float* msg_W1  = (const float*)d_in[4];
    const float* msg_b1  = (const float*)d_in[5];
    const float* msg_W2  = (const float*)d_in[6];
    const float* msg_b2  = (const float*)d_in[7];
    const float* msg_W3  = (const float*)d_in[8];
    const float* msg_b3  = (const float*)d_in[9];
    const float* node_W1 = (const float*)d_in[10];
    const float* node_b1 = (const float*)d_in[11];
    const float* node_W2 = (const float*)d_in[12];
    const float* node_b2 = (const float*)d_in[13];
    const float* node_W3 = (const float*)d_in[14];
    const float* node_b3 = (const float*)d_in[15];
    const float* glob_W1 = (const float*)d_in[16];
    const float* glob_b1 = (const float*)d_in[17];
    const float* glob_W2 = (const float*)d_in[18];
    const float* glob_b2 = (const float*)d_in[19];
    const float* glob_W3 = (const float*)d_in[20];
    const float* glob_b3 = (const float*)d_in[21];
    float* out = (float*)d_out;

    float *pPa, *pPb, *pag, *phn;
    int *psrc, *pdst;
    __nv_bfloat16 *xH,*xL,*h1H,*h1L,*h2H,*h2L,*uH,*uL,*a1H,*a1L,*a2H,*a2L;
    __nv_bfloat16 *paH,*paL,*pbH,*pbL,*w2H,*w2L,*w3H,*w3L,*n1H,*n1L,*n2H,*n2L,*n3H,*n3L;
    cudaGetSymbolAddress((void**)&pPa, g_Pa);
    cudaGetSymbolAddress((void**)&pPb, g_Pb);
    cudaGetSymbolAddress((void**)&pag, g_aggr);
    cudaGetSymbolAddress((void**)&phn, g_hn);
    cudaGetSymbolAddress((void**)&psrc, g_src);
    cudaGetSymbolAddress((void**)&pdst, g_dst);
    cudaGetSymbolAddress((void**)&xH, g_xH);   cudaGetSymbolAddress((void**)&xL, g_xL);
    cudaGetSymbolAddress((void**)&h1H, g_h1H); cudaGetSymbolAddress((void**)&h1L, g_h1L);
    cudaGetSymbolAddress((void**)&h2H, g_h2H); cudaGetSymbolAddress((void**)&h2L, g_h2L);
    cudaGetSymbolAddress((void**)&uH, g_uH);   cudaGetSymbolAddress((void**)&uL, g_uL);
    cudaGetSymbolAddress((void**)&a1H, g_a1H); cudaGetSymbolAddress((void**)&a1L, g_a1L);
    cudaGetSymbolAddress((void**)&a2H, g_a2H); cudaGetSymbolAddress((void**)&a2L, g_a2L);
    cudaGetSymbolAddress((void**)&paH, g_wpaH); cudaGetSymbolAddress((void**)&paL, g_wpaL);
    cudaGetSymbolAddress((void**)&pbH, g_wpbH); cudaGetSymbolAddress((void**)&pbL, g_wpbL);
    cudaGetSymbolAddress((void**)&w2H, g_w2H);  cudaGetSymbolAddress((void**)&w2L, g_w2L);
    cudaGetSymbolAddress((void**)&w3H, g_w3H);  cudaGetSymbolAddress((void**)&w3L, g_w3L);
    cudaGetSymbolAddress((void**)&n1H, g_wn1H); cudaGetSymbolAddress((void**)&n1L, g_wn1L);
    cudaGetSymbolAddress((void**)&n2H, g_wn2H); cudaGetSymbolAddress((void**)&n2L, g_wn2L);
    cudaGetSymbolAddress((void**)&n3H, g_wn3H); cudaGetSymbolAddress((void**)&n3L, g_wn3L);

    cudaFuncSetAttribute(tmma_k<0>, cudaFuncAttributeMaxDynamicSharedMemorySize, TSMEM);
    cudaFuncSetAttribute(tmma_k<2>, cudaFuncAttributeMaxDynamicSharedMemorySize, TSMEM);

    const int NE = NEDGES, NN = NNODES;

    detect_k<<<1, 64>>>(eidx, batch, NN);
    convert_k<<<(NE + 255) / 256, 256>>>(eidx, batch, NE, NN);
    zero_k<<<4096, 256>>>();
    padzero_k<<<2048, 256>>>();

    // weight + x splits
    wprep_k<<<(300*128 + 255)/256, 256>>>(msg_W1,           128, 300, 300, paH, paL, 128);
    wprep_k<<<(300*128 + 255)/256, 256>>>(msg_W1 + 128*300, 128, 300, 300, pbH, pbL, 128);
    wprep_k<<<(300*320 + 255)/256, 256>>>(msg_W2,           300, 300, 300, w2H, w2L, 320);
    wprep_k<<<(128*320 + 255)/256, 256>>>(msg_W3,           300, 128, 128, w3H, w3L, 320);
    wprep_k<<<(300*256 + 255)/256, 256>>>(node_W1,          256, 300, 300, n1H, n1L, 256);
    wprep_k<<<(300*320 + 255)/256, 256>>>(node_W2,          300, 300, 300, n2H, n2L, 320);
    wprep_k<<<(128*320 + 255)/256, 256>>>(node_W3,          300, 128, 128, n3H, n3L, 320);
    split_k<<<(NN * NF / 2 + 255)/256, 256>>>(x, xH, xL, NN * NF / 2);

    const int MT_N = (NN + 127) / 128;
    const int MT_E = (ECHUNK + 127) / 128;

    // node projections: Pa = x@W1a + b1 ; Pb = x@W1b  (fp32 out, gathered later)
    tmma_k<0><<<dim3(5, MT_N), 256, TSMEM>>>(NN, HID, NF, xH, xL,
        paH, paL, msg_b1, pPa, HID, 0, nullptr, nullptr, 0, nullptr);
    tmma_k<0><<<dim3(5, MT_N), 256, TSMEM>>>(NN, HID, NF, xH, xL,
        pbH, pbL, nullptr, pPb, HID, 0, nullptr, nullptr, 0, nullptr);

    // edge pipeline, chunked
    for (int c = 0; c < NCHUNK; c++) {
        const int e0 = c * ECHUNK;
        const int Mc = ECHUNK;
        edge1_k<<<dim3((Mc + BM - 1)/BM, (HID + BN - 1)/BN), 256>>>(Mc, HID, EF,
            eattr + (size_t)e0 * EF, EF,
            msg_W1 + (size_t)(2 * NF) * HID, HID,
            h1H, h1L, KP, pdst + e0, psrc + e0, pPa, pPb, HID);
        tmma_k<0><<<dim3(5, MT_E), 256, TSMEM>>>(Mc, HID, KP, h1H, h1L,
            w2H, w2L, msg_b2, nullptr, 0, 1, h2H, h2L, KP, nullptr);
        tmma_k<2><<<dim3(2, MT_E), 256, TSMEM>>>(Mc, MSGD, KP, h2H, h2L,
            w3H, w3L, msg_b3, pag, MSGD, 0, nullptr, nullptr, 0, pdst + e0);
    }

    // node MLP
    concat_k<<<(NN * 128 + 255) / 256, 256>>>(x, NN);
    tmma_k<0><<<dim3(5, MT_N), 256, TSMEM>>>(NN, HID, 256, uH, uL,
        n1H, n1L, node_b1, nullptr, 0, 1, a1H, a1L, KP, nullptr);
    tmma_k<0><<<dim3(5, MT_N), 256, TSMEM>>>(NN, HID, KP, a1H, a1L,
        n2H, n2L, node_b2, nullptr, 0, 1, a2H, a2L, KP, nullptr);
    tmma_k<0><<<dim3(2, MT_N), 256, TSMEM>>>(NN, NHID, KP, a2H, a2L,
        n3H, n3L, node_b3, phn, NHID, 0, nullptr, nullptr, 0, nullptr);

    // pool + global MLP
    pool_k<<<(NN * NHID + 255) / 256, 256>>>(phn, NN);
    gmlp_k<<<NGRAPH, NHID>>>(glob_W1, glob_b1, glob_W2, glob_b2,
                             glob_W3, glob_b3, out);
}

// round 13
// speedup vs baseline: 1.0368x; 1.0368x over previous
#include <cuda_runtime.h>
#include <cuda_bf16.h>
#include <cstdint>

#define NNODES 50000
#define NEDGES 800000
#define NF     128
#define EF     32
#define HID    300
#define MSGD   128
#define NHID   128
#define NGRAPH 64

#define ECHUNK 200000
#define NCHUNK (NEDGES / ECHUNK)

typedef unsigned long long u64;

// ---------------------------------------------------------------------------
// Scratch (__device__ globals; total ~1.07GB, < 2GB for GOTPCREL safety)
// ---------------------------------------------------------------------------
__device__ float g_Pa[NNODES * HID];
__device__ float g_Pb[NNODES * HID];
__device__ float g_h1a[(size_t)ECHUNK * HID];   // h1 double buffer (stream overlap)
__device__ float g_h1b[(size_t)ECHUNK * HID];
__device__ float g_h2[(size_t)ECHUNK * HID];
__device__ float g_aggr[NNODES * MSGD];
__device__ float g_u[NNODES * (NF + MSGD)];
__device__ float g_n1[NNODES * HID];
__device__ float g_n2[NNODES * HID];
__device__ float g_hn[NNODES * NHID];
__device__ float g_pool[NGRAPH * NHID];
__device__ float g_cnt[NGRAPH];
__device__ int   g_src[NEDGES];
__device__ int   g_dst[NEDGES];
__device__ int   g_batch[NNODES];
__device__ int   g_e64;
__device__ int   g_b64;

// split-transposed weights: Wt[n][kpad] bf16 hi/lo
__device__ __nv_bfloat16 g_wpaH[300*128], g_wpaL[300*128];
__device__ __nv_bfloat16 g_wpbH[300*128], g_wpbL[300*128];
__device__ __nv_bfloat16 g_w2H [300*320], g_w2L [300*320];
__device__ __nv_bfloat16 g_w3H [128*320], g_w3L [128*320];
__device__ __nv_bfloat16 g_n1H [300*256], g_n1L [300*256];
__device__ __nv_bfloat16 g_n2H [300*320], g_n2L [300*320];
__device__ __nv_bfloat16 g_n3H [128*320], g_n3L [128*320];

// ---------------------------------------------------------------------------
// PTX helpers (sm_80-compatible: ldmatrix + mma.sync — legal on sm_100 target)
// ---------------------------------------------------------------------------
__device__ __forceinline__ uint32_t smem_u32(const void* p) {
    uint32_t a;
    asm("{ .reg .u64 t; cvta.to.shared.u64 t, %1; cvt.u32.u64 %0, t; }"
        : "=r"(a) : "l"(p));
    return a;
}
__device__ __forceinline__ void ldm_x4(uint32_t* r, uint32_t addr) {
    asm volatile("ldmatrix.sync.aligned.m8n8.x4.shared.b16 {%0,%1,%2,%3}, [%4];"
        : "=r"(r[0]), "=r"(r[1]), "=r"(r[2]), "=r"(r[3]) : "r"(addr));
}
__device__ __forceinline__ void mma16816(float* c, const uint32_t* a,
                                         const uint32_t* b) {
    asm volatile(
        "mma.sync.aligned.m16n8k16.row.col.f32.bf16.bf16.f32 "
        "{%0,%1,%2,%3}, {%4,%5,%6,%7}, {%8,%9}, {%0,%1,%2,%3};"
        : "+f"(c[0]), "+f"(c[1]), "+f"(c[2]), "+f"(c[3])
        : "r"(a[0]), "r"(a[1]), "r"(a[2]), "r"(a[3]), "r"(b[0]), "r"(b[1]));
}

// ---------------------------------------------------------------------------
// small kernels
// ---------------------------------------------------------------------------
__global__ void detect_k(const int* __restrict__ e, const int* __restrict__ b, int nn) {
    __shared__ int se, sb;
    int t = threadIdx.x;
    if (t == 0) { se = 1; sb = 1; }
    __syncthreads();
    if (e[2 * t + 1] != 0) se = 0;
    int w = nn - 1 - 2 * t;
    if (b[w] != 0) sb = 0;
    __syncthreads();
    if (t == 0) { g_e64 = se; g_b64 = sb; }
}
__global__ void convert_k(const int* __restrict__ e, const int* __restrict__ b,
                          int ne, int nn) {
    int i = blockIdx.x * blockDim.x + threadIdx.x;
    int e64 = g_e64, b64 = g_b64;
    if (i < ne) {
        if (e64) { g_src[i] = e[2 * i]; g_dst[i] = e[2 * (ne + i)]; }
        else     { g_src[i] = e[i];     g_dst[i] = e[ne + i]; }
    }
    if (i < nn) g_batch[i] = b64 ? b[2 * i] : b[i];
}
__global__ void zero_k() {
    long i = blockIdx.x * (long)blockDim.x + threadIdx.x;
    long stride = gridDim.x * (long)blockDim.x;
    for (long j = i; j < (long)NNODES * MSGD; j += stride) g_aggr[j] = 0.0f;
    if (i < NGRAPH * NHID) g_pool[i] = 0.0f;
    if (i < NGRAPH) g_cnt[i] = 0.0f;
}
// W[K][N] row-major (ld=ldw) -> hi/lo [N][kpad] bf16, zero-padded in k
__global__ void wprep_k(const float* __restrict__ W, int K, int Nw, int ldw,
                        __nv_bfloat16* __restrict__ hi, __nv_bfloat16* __restrict__ lo,
                        int kpad) {
    int idx = blockIdx.x * blockDim.x + threadIdx.x;
    if (idx >= Nw * kpad) return;
    int n = idx / kpad, k = idx % kpad;
    float v = (k < K) ? W[(size_t)k * ldw + n] : 0.0f;
    __nv_bfloat16 h = __float2bfloat16(v);
    hi[idx] = h;
    lo[idx] = __float2bfloat16(v - __bfloat162float(h));
}

// ---------------------------------------------------------------------------
// Tensor GEMM via mma.sync bf16 split (3 products, fp32 accum).  [R11 proven]
// ---------------------------------------------------------------------------
#define RSB 80
#define OF_AH 0
#define OF_AL 10240
#define OF_BH 20480
#define OF_BL 25600
#define TBUF  30720
#define TSMEM (2*TBUF)

template <int MODE>
__global__ void __launch_bounds__(256, 2)
tmma_k(int M, int N, int K,
       const float* __restrict__ A, int lda,
       const __nv_bfloat16* __restrict__ BH, const __nv_bfloat16* __restrict__ BL,
       int kpad,
       const float* __restrict__ bias,
       float* __restrict__ C, int ldc, int relu,
       const int* __restrict__ rdst) {
    extern __shared__ char sm[];
    const uint32_t smb = smem_u32(sm);
    const int tid = threadIdx.x;
    const int lane = tid & 31;
    const int wid = tid >> 5;
    const int wm = wid & 3, wn = wid >> 2;
    const int col0 = blockIdx.x * 64;
    const int row0 = blockIdx.y * 128;

    float cc[2][4][4];
#pragma unroll
    for (int a = 0; a < 2; a++)
#pragma unroll
        for (int b = 0; b < 4; b++)
#pragma unroll
            for (int c = 0; c < 4; c++) cc[a][b][c] = 0.0f;

    float4 va[4];
    uint4 vbh, vbl;

    const int rowA = tid >> 1, halfA = tid & 1;
    const int nB = tid >> 2, segB = tid & 3;

    auto ldgA = [&](int k0) {
        int grow = row0 + rowA;
        const float* p = A + (size_t)grow * lda + k0 + halfA * 16;
        if (grow < M && k0 + halfA * 16 + 16 <= K) {
            va[0] = ((const float4*)p)[0]; va[1] = ((const float4*)p)[1];
            va[2] = ((const float4*)p)[2]; va[3] = ((const float4*)p)[3];
        } else {
            float* vf = (float*)va;
#pragma unroll
            for (int j = 0; j < 16; j++) {
                int gk = k0 + halfA * 16 + j;
                vf[j] = (grow < M && gk < K) ? p[j] : 0.0f;
            }
        }
    };
    auto ldgB = [&](int k0) {
        if (col0 + nB < N) {
            vbh = *(const uint4*)(BH + (size_t)(col0 + nB) * kpad + k0 + segB * 8);
            vbl = *(const uint4*)(BL + (size_t)(col0 + nB) * kpad + k0 + segB * 8);
        } else {
            vbh = make_uint4(0, 0, 0, 0);
            vbl = make_uint4(0, 0, 0, 0);
        }
    };
    auto sts = [&](int buf) {
        uint32_t hw[8], lw[8];
        const float* vf = (const float*)va;
#pragma unroll
        for (int j = 0; j < 8; j++) {
            float v0 = vf[2 * j], v1 = vf[2 * j + 1];
            __nv_bfloat16 h0 = __float2bfloat16(v0), h1 = __float2bfloat16(v1);
            __nv_bfloat16 l0 = __float2bfloat16(v0 - __bfloat162float(h0));
            __nv_bfloat16 l1 = __float2bfloat16(v1 - __bfloat162float(h1));
            hw[j] = (uint32_t)__bfloat16_as_ushort(h0) |
                    ((uint32_t)__bfloat16_as_ushort(h1) << 16);
            lw[j] = (uint32_t)__bfloat16_as_ushort(l0) |
                    ((uint32_t)__bfloat16_as_ushort(l1) << 16);
        }
        char* ba = sm + buf + OF_AH + rowA * RSB + halfA * 32;
        *(uint4*)(ba +  0) = make_uint4(hw[0], hw[1], hw[2], hw[3]);
        *(uint4*)(ba + 16) = make_uint4(hw[4], hw[5], hw[6], hw[7]);
        char* bl_ = sm + buf + OF_AL + rowA * RSB + halfA * 32;
        *(uint4*)(bl_ +  0) = make_uint4(lw[0], lw[1], lw[2], lw[3]);
        *(uint4*)(bl_ + 16) = make_uint4(lw[4], lw[5], lw[6], lw[7]);
        *(uint4*)(sm + buf + OF_BH + nB * RSB + segB * 16) = vbh;
        *(uint4*)(sm + buf + OF_BL + nB * RSB + segB * 16) = vbl;
    };
    auto compute = [&](int buf) {
#pragma unroll
        for (int k16 = 0; k16 < 32; k16 += 16) {
            uint32_t ah[2][4], al[2][4], bh[4][2], bl2[4][2];
#pragma unroll
            for (int mt = 0; mt < 2; mt++) {
                uint32_t ad = smb + buf + OF_AH
                    + (uint32_t)(wm * 32 + mt * 16 + (lane & 15)) * RSB
                    + (uint32_t)(k16 + (lane >> 4) * 8) * 2;
                ldm_x4(ah[mt], ad);
                ldm_x4(al[mt], ad + (OF_AL - OF_AH));
            }
            {
                int g = lane >> 3, r = lane & 7;
#pragma unroll
                for (int np = 0; np < 2; np++) {
                    uint32_t bd = smb + buf + OF_BH
                        + (uint32_t)(wn * 32 + np * 16 + ((g >> 1) & 1) * 8 + r) * RSB
                        + (uint32_t)(k16 + (g & 1) * 8) * 2;
                    uint32_t t4[4];
                    ldm_x4(t4, bd);
                    bh[np * 2][0] = t4[0]; bh[np * 2][1] = t4[1];
                    bh[np * 2 + 1][0] = t4[2]; bh[np * 2 + 1][1] = t4[3];
                    ldm_x4(t4, bd + (OF_BL - OF_BH));
                    bl2[np * 2][0] = t4[0]; bl2[np * 2][1] = t4[1];
                    bl2[np * 2 + 1][0] = t4[2]; bl2[np * 2 + 1][1] = t4[3];
                }
            }
#pragma unroll
            for (int mt = 0; mt < 2; mt++)
#pragma unroll
                for (int nt = 0; nt < 4; nt++) {
                    mma16816(cc[mt][nt], ah[mt], bh[nt]);
                    mma16816(cc[mt][nt], ah[mt], bl2[nt]);
                    mma16816(cc[mt][nt], al[mt], bh[nt]);
                }
        }
    };

    const int nst = (K + 31) / 32;
    ldgA(0); ldgB(0);
    sts(0);
    __syncthreads();
    for (int s = 0; s < nst; s++) {
        const int buf = (s & 1) * TBUF;
        if (s + 1 < nst) { ldgA((s + 1) * 32); ldgB((s + 1) * 32); }
        compute(buf);
        if (s + 1 < nst) {
            sts(((s + 1) & 1) * TBUF);
            __syncthreads();
        }
    }

#pragma unroll
    for (int mt = 0; mt < 2; mt++) {
#pragma unroll
        for (int h = 0; h < 2; h++) {
            int row = row0 + wm * 32 + mt * 16 + (lane >> 2) + h * 8;
            if (row >= M) continue;
            int dn = (MODE == 2) ? rdst[row] : 0;
#pragma unroll
            for (int nt = 0; nt < 4; nt++) {
                int col = col0 + wn * 32 + nt * 8 + (lane & 3) * 2;
                if (col >= N) continue;
                float v0 = cc[mt][nt][h * 2], v1 = cc[mt][nt][h * 2 + 1];
                if (bias) {
                    float2 bb = *(const float2*)(bias + col);
                    v0 += bb.x; v1 += bb.y;
                }
                if (MODE == 0) {
                    if (relu) { v0 = fmaxf(v0, 0.f); v1 = fmaxf(v1, 0.f); }
                    *(float2*)(C + (size_t)row * ldc + col) = make_float2(v0, v1);
                } else {
                    atomicAdd(C + (size_t)dn * ldc + col, v0);
                    atomicAdd(C + (size_t)dn * ldc + col + 1, v1);
                }
            }
        }
    }
}

// ---------------------------------------------------------------------------
// SIMT FFMA2 SGEMM — MODE 1 (edge layer-1 gather epilogue, K=32)  [R9 proven]
// ---------------------------------------------------------------------------
#define BM 128
#define BN 128
#define BK 16
#define TM 8
#define TN 8
__device__ __forceinline__ u64 ffma2(u64 a, u64 b, u64 c) {
    u64 d;
    asm("fma.rn.f32x2 %0, %1, %2, %3;" : "=l"(d) : "l"(a), "l"(b), "l"(c));
    return d;
}
__device__ __forceinline__ u64 pack2(float lo, float hi) {
    u64 d;
    asm("mov.b64 %0, {%1, %2};" : "=l"(d) : "f"(lo), "f"(hi));
    return d;
}

template <int MODE>
__global__ void __launch_bounds__(256, 2)
sgemm_k(int M, int N, int K,
        const float* __restrict__ A, int lda,
        const float* __restrict__ B, int ldb,
        const float* __restrict__ bias,
        float* __restrict__ C, int ldc,
        int relu,
        const int* __restrict__ rdst, const int* __restrict__ rsrc,
        const float* __restrict__ Pa, const float* __restrict__ Pb, int ldp) {
    __shared__ float As[2][BK * BM];
    __shared__ float Bs[2][BK * BN];
    const int row0 = blockIdx.x * BM;
    const int col0 = blockIdx.y * BN;
    const int tid = threadIdx.x;
    const int tr = tid / (BN / TN);
    const int tc = tid % (BN / TN);
    const int aRow = tid / (BK / 4), aCol4 = tid % (BK / 4);
    const int bRow = tid / (BN / 4), bCol4 = tid % (BN / 4);

    u64 acc2[TM / 2][TN];
#pragma unroll
    for (int i = 0; i < TM / 2; i++)
#pragma unroll
        for (int j = 0; j < TN; j++) acc2[i][j] = 0ull;

    float4 va[2], vb[2];
    auto ldg = [&](int k0) {
#pragma unroll
        for (int r = 0; r < 2; r++) {
            int grow = row0 + aRow + r * 64, gk = k0 + aCol4 * 4;
            va[r] = make_float4(0.f, 0.f, 0.f, 0.f);
            if (grow < M && gk < K)
                va[r] = *(const float4*)(A + (size_t)grow * lda + gk);
        }
#pragma unroll
        for (int r = 0; r < 2; r++) {
            int gk = k0 + bRow + r * 8, gcol = col0 + bCol4 * 4;
            vb[r] = make_float4(0.f, 0.f, 0.f, 0.f);
            if (gk < K && gcol < N)
                vb[r] = *(const float4*)(B + (size_t)gk * ldb + gcol);
        }
    };
    auto sts = [&](int buf) {
#pragma unroll
        for (int r = 0; r < 2; r++) {
            As[buf][(aCol4 * 4 + 0) * BM + aRow + r * 64] = va[r].x;
            As[buf][(aCol4 * 4 + 1) * BM + aRow + r * 64] = va[r].y;
            As[buf][(aCol4 * 4 + 2) * BM + aRow + r * 64] = va[r].z;
            As[buf][(aCol4 * 4 + 3) * BM + aRow + r * 64] = va[r].w;
        }
#pragma unroll
        for (int r = 0; r < 2; r++)
            *(float4*)(&Bs[buf][(bRow + r * 8) * BN + bCol4 * 4]) = vb[r];
    };

    const int nst = (K + BK - 1) / BK;
    ldg(0); sts(0);
    __syncthreads();
    for (int s = 0; s < nst; s++) {
        const int buf = s & 1;
        if (s + 1 < nst) ldg((s + 1) * BK);
#pragma unroll
        for (int kk = 0; kk < BK; kk++) {
            ulonglong2 pa0 = *(const ulonglong2*)&As[buf][kk * BM + tr * TM];
            ulonglong2 pa1 = *(const ulonglong2*)&As[buf][kk * BM + tr * TM + 4];
            u64 ra2[TM / 2] = {pa0.x, pa0.y, pa1.x, pa1.y};
            float4 b0 = *(const float4*)&Bs[buf][kk * BN + tc * TN];
            float4 b1 = *(const float4*)&Bs[buf][kk * BN + tc * TN + 4];
            u64 rb2[TN];
            rb2[0] = pack2(b0.x, b0.x); rb2[1] = pack2(b0.y, b0.y);
            rb2[2] = pack2(b0.z, b0.z); rb2[3] = pack2(b0.w, b0.w);
            rb2[4] = pack2(b1.x, b1.x); rb2[5] = pack2(b1.y, b1.y);
            rb2[6] = pack2(b1.z, b1.z); rb2[7] = pack2(b1.w, b1.w);
#pragma unroll
            for (int i = 0; i < TM / 2; i++)
#pragma unroll
                for (int j = 0; j < TN; j++)
                    acc2[i][j] = ffma2(ra2[i], rb2[j], acc2[i][j]);
        }
        if (s + 1 < nst) { sts(buf ^ 1); __syncthreads(); }
    }

#pragma unroll
    for (int i2 = 0; i2 < TM / 2; i2++) {
        float2 f[TN];
#pragma unroll
        for (int j = 0; j < TN; j++) f[j] = *(float2*)&acc2[i2][j];
#pragma unroll
        for (int w = 0; w < 2; w++) {
            int row = row0 + tr * TM + 2 * i2 + w;
            if (row >= M) continue;
            int dn = 0, sn = 0;
            if (MODE == 1) { dn = rdst[row]; sn = rsrc[row]; }
            if (MODE == 2) { dn = rdst[row]; }
#pragma unroll
            for (int j = 0; j < TN; j += 4) {
                int col = col0 + tc * TN + j;
                if (col >= N) continue;
                float4 v;
                if (w == 0) v = make_float4(f[j].x, f[j+1].x, f[j+2].x, f[j+3].x);
                else        v = make_float4(f[j].y, f[j+1].y, f[j+2].y, f[j+3].y);
                if (bias) {
                    float4 bb = *(const float4*)(bias + col);
                    v.x += bb.x; v.y += bb.y; v.z += bb.z; v.w += bb.w;
                }
                if (MODE == 0) {
                    if (relu) {
                        v.x = fmaxf(v.x, 0.f); v.y = fmaxf(v.y, 0.f);
                        v.z = fmaxf(v.z, 0.f); v.w = fmaxf(v.w, 0.f);
                    }
                    *(float4*)(C + (size_t)row * ldc + col) = v;
                } else if (MODE == 1) {
                    float4 a4 = *(const float4*)(Pa + (size_t)dn * ldp + col);
                    float4 b4 = *(const float4*)(Pb + (size_t)sn * ldp + col);
                    v.x = fmaxf(v.x + a4.x + b4.x, 0.f);
                    v.y = fmaxf(v.y + a4.y + b4.y, 0.f);
                    v.z = fmaxf(v.z + a4.z + b4.z, 0.f);
                    v.w = fmaxf(v.w + a4.w + b4.w, 0.f);
                    *(float4*)(C + (size_t)row * ldc + col) = v;
                } else {
                    float* p = C + (size_t)dn * ldc + col;
                    atomicAdd(p + 0, v.x); atomicAdd(p + 1, v.y);
                    atomicAdd(p + 2, v.z); atomicAdd(p + 3, v.w);
                }
            }
        }
    }
}

__global__ void concat_k(const float* __restrict__ x, int nn) {
    int idx = blockIdx.x * blockDim.x + threadIdx.x;
    int n = idx >> 8, c = idx & 255;
    if (n < nn)
        g_u[idx] = (c < NF) ? x[n * NF + c] : g_aggr[n * MSGD + (c - NF)];
}
__global__ void pool_k(const float* __restrict__ h, int nn) {
    int idx = blockIdx.x * blockDim.x + threadIdx.x;
    int n = idx >> 7, c = idx & 127;
    if (n < nn) {
        int b = g_batch[n];
        atomicAdd(&g_pool[b * NHID + c], h[idx]);
        if (c == 0) atomicAdd(&g_cnt[b], 1.0f);
    }
}
__global__ void gmlp_k(const float* __restrict__ W1, const float* __restrict__ b1,
                       const float* __restrict__ W2, const float* __restrict__ b2,
                       const float* __restrict__ W3, const float* __restrict__ b3,
                       float* __restrict__ out) {
    int g = blockIdx.x, t = threadIdx.x;
    __shared__ float s_in[NHID], s_h[NHID];
    float c = fmaxf(g_cnt[g], 1.0f);
    s_in[t] = g_pool[g * NHID + t] / c;
    __syncthreads();
    float a = b1[t];
    for (int k = 0; k < NHID; k++) a += s_in[k] * W1[k * NHID + t];
    s_h[t] = fmaxf(a, 0.0f);
    __syncthreads();
    a = b2[t];
    for (int k = 0; k < NHID; k++) a += s_h[k] * W2[k * NHID + t];
    a = fmaxf(a, 0.0f);
    __syncthreads();
    s_in[t] = a * W3[t];
    __syncthreads();
    for (int s = 64; s > 0; s >>= 1) {
        if (t < s) s_in[t] += s_in[t + s];
        __syncthreads();
    }
    if (t == 0) out[g] = s_in[0] + b3[0];
}

// ---------------------------------------------------------------------------
// launch — edge1 (FMA pipe) overlapped with L2/L3 (tensor pipe) via a second
// stream, expressed with events so graph capture builds the DAG.
// ---------------------------------------------------------------------------
extern "C" void kernel_launch(void* const* d_in, const int* in_sizes, int n_in,
                              void* d_out, int out_size) {
    const float* x       = (const float*)d_in[0];
    const int*   eidx    = (const int*)d_in[1];
    const float* eattr   = (const float*)d_in[2];
    const int*   batch   = (const int*)d_in[3];
    const float* msg_W1  = (const float*)d_in[4];
    const float* msg_b1  = (const float*)d_in[5];
    const float* msg_W2  = (const float*)d_in[6];
    const float* msg_b2  = (const float*)d_in[7];
    const float* msg_W3  = (const float*)d_in[8];
    const float* msg_b3  = (const float*)d_in[9];
    const float* node_W1 = (const float*)d_in[10];
    const float* node_b1 = (const float*)d_in[11];
    const float* node_W2 = (const float*)d_in[12];
    const float* node_b2 = (const float*)d_in[13];
    const float* node_W3 = (const float*)d_in[14];
    const float* node_b3 = (const float*)d_in[15];
    const float* glob_W1 = (const float*)d_in[16];
    const float* glob_b1 = (const float*)d_in[17];
    const float* glob_W2 = (const float*)d_in[18];
    const float* glob_b2 = (const float*)d_in[19];
    const float* glob_W3 = (const float*)d_in[20];
    const float* glob_b3 = (const float*)d_in[21];
    float* out = (float*)d_out;

    float *pPa, *pPb, *ph1a, *ph1b, *ph2, *pag, *pu, *pn1, *pn2, *phn;
    int *psrc, *pdst;
    __nv_bfloat16 *paH,*paL,*pbH,*pbL,*w2H,*w2L,*w3H,*w3L,*n1H,*n1L,*n2H,*n2L,*n3H,*n3L;
    cudaGetSymbolAddress((void**)&pPa, g_Pa);
    cudaGetSymbolAddress((void**)&pPb, g_Pb);
    cudaGetSymbolAddress((void**)&ph1a, g_h1a);
    cudaGetSymbolAddress((void**)&ph1b, g_h1b);
    cudaGetSymbolAddress((void**)&ph2, g_h2);
    cudaGetSymbolAddress((void**)&pag, g_aggr);
    cudaGetSymbolAddress((void**)&pu, g_u);
    cudaGetSymbolAddress((void**)&pn1, g_n1);
    cudaGetSymbolAddress((void**)&pn2, g_n2);
    cudaGetSymbolAddress((void**)&phn, g_hn);
    cudaGetSymbolAddress((void**)&psrc, g_src);
    cudaGetSymbolAddress((void**)&pdst, g_dst);
    cudaGetSymbolAddress((void**)&paH, g_wpaH); cudaGetSymbolAddress((void**)&paL, g_wpaL);
    cudaGetSymbolAddress((void**)&pbH, g_wpbH); cudaGetSymbolAddress((void**)&pbL, g_wpbL);
    cudaGetSymbolAddress((void**)&w2H, g_w2H);  cudaGetSymbolAddress((void**)&w2L, g_w2L);
    cudaGetSymbolAddress((void**)&w3H, g_w3H);  cudaGetSymbolAddress((void**)&w3L, g_w3L);
    cudaGetSymbolAddress((void**)&n1H, g_n1H);  cudaGetSymbolAddress((void**)&n1L, g_n1L);
    cudaGetSymbolAddress((void**)&n2H, g_n2H);  cudaGetSymbolAddress((void**)&n2L, g_n2L);
    cudaGetSymbolAddress((void**)&n3H, g_n3H);  cudaGetSymbolAddress((void**)&n3L, g_n3L);

    cudaFuncSetAttribute(tmma_k<0>, cudaFuncAttributeMaxDynamicSharedMemorySize, TSMEM);
    cudaFuncSetAttribute(tmma_k<2>, cudaFuncAttributeMaxDynamicSharedMemorySize, TSMEM);

    // side stream + events (host objects; created once, reused every call —
    // same work issued on every invocation, so determinism holds)
    static cudaStream_t s2 = nullptr;
    static cudaEvent_t evPrep, evE[NCHUNK], evL2[NCHUNK];
    if (!s2) {
        cudaStreamCreateWithFlags(&s2, cudaStreamNonBlocking);
        cudaEventCreateWithFlags(&evPrep, cudaEventDisableTiming);
        for (int i = 0; i < NCHUNK; i++) {
            cudaEventCreateWithFlags(&evE[i], cudaEventDisableTiming);
            cudaEventCreateWithFlags(&evL2[i], cudaEventDisableTiming);
        }
    }

    const int NE = NEDGES, NN = NNODES;

    detect_k<<<1, 64>>>(eidx, batch, NN);
    convert_k<<<(NE + 255) / 256, 256>>>(eidx, batch, NE, NN);
    zero_k<<<4096, 256>>>();

    wprep_k<<<(300*128 + 255)/256, 256>>>(msg_W1,           128, 300, 300, paH, paL, 128);
    wprep_k<<<(300*128 + 255)/256, 256>>>(msg_W1 + 128*300, 128, 300, 300, pbH, pbL, 128);
    wprep_k<<<(300*320 + 255)/256, 256>>>(msg_W2,           300, 300, 300, w2H, w2L, 320);
    wprep_k<<<(128*320 + 255)/256, 256>>>(msg_W3,           300, 128, 128, w3H, w3L, 320);
    wprep_k<<<(300*256 + 255)/256, 256>>>(node_W1,          256, 300, 300, n1H, n1L, 256);
    wprep_k<<<(300*320 + 255)/256, 256>>>(node_W2,          300, 300, 300, n2H, n2L, 320);
    wprep_k<<<(128*320 + 255)/256, 256>>>(node_W3,          300, 128, 128, n3H, n3L, 320);

    const int MT_N = (NN + 127) / 128;
    const int MT_E = (ECHUNK + 127) / 128;

    // Pa/Pb projections (tensor, main stream) — edge1 needs these
    tmma_k<0><<<dim3(5, MT_N), 256, TSMEM>>>(NN, HID, NF, x, NF,
        paH, paL, 128, msg_b1, pPa, HID, 0, nullptr);
    tmma_k<0><<<dim3(5, MT_N), 256, TSMEM>>>(NN, HID, NF, x, NF,
        pbH, pbL, 128, nullptr, pPb, HID, 0, nullptr);
    cudaEventRecord(evPrep, 0);
    cudaStreamWaitEvent(s2, evPrep, 0);

    // edge pipeline: edge1[c] on s2 (FMA pipe) overlaps L2/L3[c-1] on main
    // stream (tensor pipe); h1 double-buffered, reuse gated by evL2.
    float* h1buf[2] = {ph1a, ph1b};
    for (int c = 0; c < NCHUNK; c++) {
        const int e0 = c * ECHUNK;
        const int Mc = ECHUNK;
        float* ph1 = h1buf[c & 1];

        if (c >= 2) cudaStreamWaitEvent(s2, evL2[c - 2], 0);
        sgemm_k<1><<<dim3((Mc + BM - 1)/BM, (HID + BN - 1)/BN), 256, 0, s2>>>(
            Mc, HID, EF, eattr + (size_t)e0 * EF, EF,
            msg_W1 + (size_t)(2 * NF) * HID, HID, nullptr, ph1, HID, 1,
            pdst + e0, psrc + e0, pPa, pPb, HID);
        cudaEventRecord(evE[c], s2);

        cudaStreamWaitEvent(0, evE[c], 0);
        tmma_k<0><<<dim3(5, MT_E), 256, TSMEM>>>(Mc, HID, HID,
            ph1, HID, w2H, w2L, 320, msg_b2, ph2, HID, 1, nullptr);
        cudaEventRecord(evL2[c], 0);
        tmma_k<2><<<dim3(2, MT_E), 256, TSMEM>>>(Mc, MSGD, HID,
            ph2, HID, w3H, w3L, 320, msg_b3, pag, MSGD, 0, pdst + e0);
    }

    // node MLP (tensor, main stream; aggr complete after L3[last])
    concat_k<<<(NN * 256 + 255) / 256, 256>>>(x, NN);
    tmma_k<0><<<dim3(5, MT_N), 256, TSMEM>>>(NN, HID, NF + MSGD, pu, NF + MSGD,
        n1H, n1L, 256, node_b1, pn1, HID, 1, nullptr);
    tmma_k<0><<<dim3(5, MT_N), 256, TSMEM>>>(NN, HID, HID, pn1, HID,
        n2H, n2L, 320, node_b2, pn2, HID, 1, nullptr);
    tmma_k<0><<<dim3(2, MT_N), 256, TSMEM>>>(NN, NHID, HID, pn2, HID,
        n3H, n3L, 320, node_b3, phn, NHID, 0, nullptr);

    pool_k<<<(NN * NHID + 255) / 256, 256>>>(phn, NN);
    gmlp_k<<<NGRAPH, NHID>>>(glob_W1, glob_b1, glob_W2, glob_b2,
                             glob_W3, glob_b3, out);
}

// round 15
// speedup vs baseline: 1.0461x; 1.0089x over previous
#include <cuda_runtime.h>
#include <cuda_bf16.h>
#include <cstdint>

#define NNODES 50000
#define NEDGES 800000
#define NF     128
#define EF     32
#define HID    300
#define MSGD   128
#define NHID   128
#define NGRAPH 64

#define ECHUNK 200000
#define NCHUNK (NEDGES / ECHUNK)

typedef unsigned long long u64;

// ---------------------------------------------------------------------------
// Scratch (__device__ globals; total ~1.31GB, < 2GB for GOTPCREL safety)
// ---------------------------------------------------------------------------
__device__ float g_Pa[NNODES * HID];
__device__ float g_Pb[NNODES * HID];
__device__ float g_h1a[(size_t)ECHUNK * HID];   // h1 double buffer (edge1 overlap)
__device__ float g_h1b[(size_t)ECHUNK * HID];
__device__ float g_h2a[(size_t)ECHUNK * HID];   // h2 double buffer (L3 overlap)
__device__ float g_h2b[(size_t)ECHUNK * HID];
__device__ float g_aggr[NNODES * MSGD];
__device__ float g_u[NNODES * (NF + MSGD)];
__device__ float g_n1[NNODES * HID];
__device__ float g_n2[NNODES * HID];
__device__ float g_hn[NNODES * NHID];
__device__ float g_pool[NGRAPH * NHID];
__device__ float g_cnt[NGRAPH];
__device__ int   g_src[NEDGES];
__device__ int   g_dst[NEDGES];
__device__ int   g_batch[NNODES];
__device__ int   g_e64;
__device__ int   g_b64;

// split-transposed weights: Wt[n][kpad] bf16 hi/lo
__device__ __nv_bfloat16 g_wpaH[300*128], g_wpaL[300*128];
__device__ __nv_bfloat16 g_wpbH[300*128], g_wpbL[300*128];
__device__ __nv_bfloat16 g_w2H [300*320], g_w2L [300*320];
__device__ __nv_bfloat16 g_w3H [128*320], g_w3L [128*320];
__device__ __nv_bfloat16 g_n1H [300*256], g_n1L [300*256];
__device__ __nv_bfloat16 g_n2H [300*320], g_n2L [300*320];
__device__ __nv_bfloat16 g_n3H [128*320], g_n3L [128*320];

// ---------------------------------------------------------------------------
// PTX helpers (sm_80-compatible: ldmatrix + mma.sync — legal on sm_100 target)
// ---------------------------------------------------------------------------
__device__ __forceinline__ uint32_t smem_u32(const void* p) {
    uint32_t a;
    asm("{ .reg .u64 t; cvta.to.shared.u64 t, %1; cvt.u32.u64 %0, t; }"
        : "=r"(a) : "l"(p));
    return a;
}
__device__ __forceinline__ void ldm_x4(uint32_t* r, uint32_t addr) {
    asm volatile("ldmatrix.sync.aligned.m8n8.x4.shared.b16 {%0,%1,%2,%3}, [%4];"
        : "=r"(r[0]), "=r"(r[1]), "=r"(r[2]), "=r"(r[3]) : "r"(addr));
}
__device__ __forceinline__ void mma16816(float* c, const uint32_t* a,
                                         const uint32_t* b) {
    asm volatile(
        "mma.sync.aligned.m16n8k16.row.col.f32.bf16.bf16.f32 "
        "{%0,%1,%2,%3}, {%4,%5,%6,%7}, {%8,%9}, {%0,%1,%2,%3};"
        : "+f"(c[0]), "+f"(c[1]), "+f"(c[2]), "+f"(c[3])
        : "r"(a[0]), "r"(a[1]), "r"(a[2]), "r"(a[3]), "r"(b[0]), "r"(b[1]));
}

// ---------------------------------------------------------------------------
// small kernels
// ---------------------------------------------------------------------------
__global__ void detect_k(const int* __restrict__ e, const int* __restrict__ b, int nn) {
    __shared__ int se, sb;
    int t = threadIdx.x;
    if (t == 0) { se = 1; sb = 1; }
    __syncthreads();
    if (e[2 * t + 1] != 0) se = 0;
    int w = nn - 1 - 2 * t;
    if (b[w] != 0) sb = 0;
    __syncthreads();
    if (t == 0) { g_e64 = se; g_b64 = sb; }
}
__global__ void convert_k(const int* __restrict__ e, const int* __restrict__ b,
                          int ne, int nn) {
    int i = blockIdx.x * blockDim.x + threadIdx.x;
    int e64 = g_e64, b64 = g_b64;
    if (i < ne) {
        if (e64) { g_src[i] = e[2 * i]; g_dst[i] = e[2 * (ne + i)]; }
        else     { g_src[i] = e[i];     g_dst[i] = e[ne + i]; }
    }
    if (i < nn) g_batch[i] = b64 ? b[2 * i] : b[i];
}
__global__ void zero_k() {
    long i = blockIdx.x * (long)blockDim.x + threadIdx.x;
    long stride = gridDim.x * (long)blockDim.x;
    for (long j = i; j < (long)NNODES * MSGD; j += stride) g_aggr[j] = 0.0f;
    if (i < NGRAPH * NHID) g_pool[i] = 0.0f;
    if (i < NGRAPH) g_cnt[i] = 0.0f;
}
// batched weight split+transpose: all 7 weights in one launch (blockIdx.y)
struct WPEnt {
    const float* W;
    __nv_bfloat16* hi;
    __nv_bfloat16* lo;
    int K, Nw, ldw, kpad;
};
struct WPArgs { WPEnt e[7]; };
__global__ void wprep_all(WPArgs a) {
    const WPEnt& w = a.e[blockIdx.y];
    int idx = blockIdx.x * blockDim.x + threadIdx.x;
    if (idx >= w.Nw * w.kpad) return;
    int n = idx / w.kpad, k = idx % w.kpad;
    float v = (k < w.K) ? w.W[(size_t)k * w.ldw + n] : 0.0f;
    __nv_bfloat16 h = __float2bfloat16(v);
    w.hi[idx] = h;
    w.lo[idx] = __float2bfloat16(v - __bfloat162float(h));
}

// ---------------------------------------------------------------------------
// Tensor GEMM via mma.sync bf16 split (3 products, fp32 accum).  [R11 proven]
// ---------------------------------------------------------------------------
#define RSB 80
#define OF_AH 0
#define OF_AL 10240
#define OF_BH 20480
#define OF_BL 25600
#define TBUF  30720
#define TSMEM (2*TBUF)

template <int MODE>
__global__ void __launch_bounds__(256, 2)
tmma_k(int M, int N, int K,
       const float* __restrict__ A, int lda,
       const __nv_bfloat16* __restrict__ BH, const __nv_bfloat16* __restrict__ BL,
       int kpad,
       const float* __restrict__ bias,
       float* __restrict__ C, int ldc, int relu,
       const int* __restrict__ rdst) {
    extern __shared__ char sm[];
    const uint32_t smb = smem_u32(sm);
    const int tid = threadIdx.x;
    const int lane = tid & 31;
    const int wid = tid >> 5;
    const int wm = wid & 3, wn = wid >> 2;
    const int col0 = blockIdx.x * 64;
    const int row0 = blockIdx.y * 128;

    float cc[2][4][4];
#pragma unroll
    for (int a = 0; a < 2; a++)
#pragma unroll
        for (int b = 0; b < 4; b++)
#pragma unroll
            for (int c = 0; c < 4; c++) cc[a][b][c] = 0.0f;

    float4 va[4];
    uint4 vbh, vbl;

    const int rowA = tid >> 1, halfA = tid & 1;
    const int nB = tid >> 2, segB = tid & 3;

    auto ldgA = [&](int k0) {
        int grow = row0 + rowA;
        const float* p = A + (size_t)grow * lda + k0 + halfA * 16;
        if (grow < M && k0 + halfA * 16 + 16 <= K) {
            va[0] = ((const float4*)p)[0]; va[1] = ((const float4*)p)[1];
            va[2] = ((const float4*)p)[2]; va[3] = ((const float4*)p)[3];
        } else {
            float* vf = (float*)va;
#pragma unroll
            for (int j = 0; j < 16; j++) {
                int gk = k0 + halfA * 16 + j;
                vf[j] = (grow < M && gk < K) ? p[j] : 0.0f;
            }
        }
    };
    auto ldgB = [&](int k0) {
        if (col0 + nB < N) {
            vbh = *(const uint4*)(BH + (size_t)(col0 + nB) * kpad + k0 + segB * 8);
            vbl = *(const uint4*)(BL + (size_t)(col0 + nB) * kpad + k0 + segB * 8);
        } else {
            vbh = make_uint4(0, 0, 0, 0);
            vbl = make_uint4(0, 0, 0, 0);
        }
    };
    auto sts = [&](int buf) {
        uint32_t hw[8], lw[8];
        const float* vf = (const float*)va;
#pragma unroll
        for (int j = 0; j < 8; j++) {
            float v0 = vf[2 * j], v1 = vf[2 * j + 1];
            __nv_bfloat16 h0 = __float2bfloat16(v0), h1 = __float2bfloat16(v1);
            __nv_bfloat16 l0 = __float2bfloat16(v0 - __bfloat162float(h0));
            __nv_bfloat16 l1 = __float2bfloat16(v1 - __bfloat162float(h1));
            hw[j] = (uint32_t)__bfloat16_as_ushort(h0) |
                    ((uint32_t)__bfloat16_as_ushort(h1) << 16);
            lw[j] = (uint32_t)__bfloat16_as_ushort(l0) |
                    ((uint32_t)__bfloat16_as_ushort(l1) << 16);
        }
        char* ba = sm + buf + OF_AH + rowA * RSB + halfA * 32;
        *(uint4*)(ba +  0) = make_uint4(hw[0], hw[1], hw[2], hw[3]);
        *(uint4*)(ba + 16) = make_uint4(hw[4], hw[5], hw[6], hw[7]);
        char* bl_ = sm + buf + OF_AL + rowA * RSB + halfA * 32;
        *(uint4*)(bl_ +  0) = make_uint4(lw[0], lw[1], lw[2], lw[3]);
        *(uint4*)(bl_ + 16) = make_uint4(lw[4], lw[5], lw[6], lw[7]);
        *(uint4*)(sm + buf + OF_BH + nB * RSB + segB * 16) = vbh;
        *(uint4*)(sm + buf + OF_BL + nB * RSB + segB * 16) = vbl;
    };
    auto compute = [&](int buf) {
#pragma unroll
        for (int k16 = 0; k16 < 32; k16 += 16) {
            uint32_t ah[2][4], al[2][4], bh[4][2], bl2[4][2];
#pragma unroll
            for (int mt = 0; mt < 2; mt++) {
                uint32_t ad = smb + buf + OF_AH
                    + (uint32_t)(wm * 32 + mt * 16 + (lane & 15)) * RSB
                    + (uint32_t)(k16 + (lane >> 4) * 8) * 2;
                ldm_x4(ah[mt], ad);
                ldm_x4(al[mt], ad + (OF_AL - OF_AH));
            }
            {
                int g = lane >> 3, r = lane & 7;
#pragma unroll
                for (int np = 0; np < 2; np++) {
                    uint32_t bd = smb + buf + OF_BH
                        + (uint32_t)(wn * 32 + np * 16 + ((g >> 1) & 1) * 8 + r) * RSB
                        + (uint32_t)(k16 + (g & 1) * 8) * 2;
                    uint32_t t4[4];
                    ldm_x4(t4, bd);
                    bh[np * 2][0] = t4[0]; bh[np * 2][1] = t4[1];
                    bh[np * 2 + 1][0] = t4[2]; bh[np * 2 + 1][1] = t4[3];
                    ldm_x4(t4, bd + (OF_BL - OF_BH));
                    bl2[np * 2][0] = t4[0]; bl2[np * 2][1] = t4[1];
                    bl2[np * 2 + 1][0] = t4[2]; bl2[np * 2 + 1][1] = t4[3];
                }
            }
#pragma unroll
            for (int mt = 0; mt < 2; mt++)
#pragma unroll
                for (int nt = 0; nt < 4; nt++) {
                    mma16816(cc[mt][nt], ah[mt], bh[nt]);
                    mma16816(cc[mt][nt], ah[mt], bl2[nt]);
                    mma16816(cc[mt][nt], al[mt], bh[nt]);
                }
        }
    };

    const int nst = (K + 31) / 32;
    ldgA(0); ldgB(0);
    sts(0);
    __syncthreads();
    for (int s = 0; s < nst; s++) {
        const int buf = (s & 1) * TBUF;
        if (s + 1 < nst) { ldgA((s + 1) * 32); ldgB((s + 1) * 32); }
        compute(buf);
        if (s + 1 < nst) {
            sts(((s + 1) & 1) * TBUF);
            __syncthreads();
        }
    }

#pragma unroll
    for (int mt = 0; mt < 2; mt++) {
#pragma unroll
        for (int h = 0; h < 2; h++) {
            int row = row0 + wm * 32 + mt * 16 + (lane >> 2) + h * 8;
            if (row >= M) continue;
            int dn = (MODE == 2) ? rdst[row] : 0;
#pragma unroll
            for (int nt = 0; nt < 4; nt++) {
                int col = col0 + wn * 32 + nt * 8 + (lane & 3) * 2;
                if (col >= N) continue;
                float v0 = cc[mt][nt][h * 2], v1 = cc[mt][nt][h * 2 + 1];
                if (bias) {
                    float2 bb = *(const float2*)(bias + col);
                    v0 += bb.x; v1 += bb.y;
                }
                if (MODE == 0) {
                    if (relu) { v0 = fmaxf(v0, 0.f); v1 = fmaxf(v1, 0.f); }
                    *(float2*)(C + (size_t)row * ldc + col) = make_float2(v0, v1);
                } else {
                    atomicAdd(C + (size_t)dn * ldc + col, v0);
                    atomicAdd(C + (size_t)dn * ldc + col + 1, v1);
                }
            }
        }
    }
}

// ---------------------------------------------------------------------------
// SIMT FFMA2 SGEMM — MODE 1 (edge layer-1 gather epilogue, K=32)  [R9 proven]
// ---------------------------------------------------------------------------
#define BM 128
#define BN 128
#define BK 16
#define TM 8
#define TN 8
__device__ __forceinline__ u64 ffma2(u64 a, u64 b, u64 c) {
    u64 d;
    asm("fma.rn.f32x2 %0, %1, %2, %3;" : "=l"(d) : "l"(a), "l"(b), "l"(c));
    return d;
}
__device__ __forceinline__ u64 pack2(float lo, float hi) {
    u64 d;
    asm("mov.b64 %0, {%1, %2};" : "=l"(d) : "f"(lo), "f"(hi));
    return d;
}

template <int MODE>
__global__ void __launch_bounds__(256, 2)
sgemm_k(int M, int N, int K,
        const float* __restrict__ A, int lda,
        const float* __restrict__ B, int ldb,
        const float* __restrict__ bias,
        float* __restrict__ C, int ldc,
        int relu,
        const int* __restrict__ rdst, const int* __restrict__ rsrc,
        const float* __restrict__ Pa, const float* __restrict__ Pb, int ldp) {
    __shared__ float As[2][BK * BM];
    __shared__ float Bs[2][BK * BN];
    const int row0 = blockIdx.x * BM;
    const int col0 = blockIdx.y * BN;
    const int tid = threadIdx.x;
    const int tr = tid / (BN / TN);
    const int tc = tid % (BN / TN);
    const int aRow = tid / (BK / 4), aCol4 = tid % (BK / 4);
    const int bRow = tid / (BN / 4), bCol4 = tid % (BN / 4);

    u64 acc2[TM / 2][TN];
#pragma unroll
    for (int i = 0; i < TM / 2; i++)
#pragma unroll
        for (int j = 0; j < TN; j++) acc2[i][j] = 0ull;

    float4 va[2], vb[2];
    auto ldg = [&](int k0) {
#pragma unroll
        for (int r = 0; r < 2; r++) {
            int grow = row0 + aRow + r * 64, gk = k0 + aCol4 * 4;
            va[r] = make_float4(0.f, 0.f, 0.f, 0.f);
            if (grow < M && gk < K)
                va[r] = *(const float4*)(A + (size_t)grow * lda + gk);
        }
#pragma unroll
        for (int r = 0; r < 2; r++) {
            int gk = k0 + bRow + r * 8, gcol = col0 + bCol4 * 4;
            vb[r] = make_float4(0.f, 0.f, 0.f, 0.f);
            if (gk < K && gcol < N)
                vb[r] = *(const float4*)(B + (size_t)gk * ldb + gcol);
        }
    };
    auto sts = [&](int buf) {
#pragma unroll
        for (int r = 0; r < 2; r++) {
            As[buf][(aCol4 * 4 + 0) * BM + aRow + r * 64] = va[r].x;
            As[buf][(aCol4 * 4 + 1) * BM + aRow + r * 64] = va[r].y;
            As[buf][(aCol4 * 4 + 2) * BM + aRow + r * 64] = va[r].z;
            As[buf][(aCol4 * 4 + 3) * BM + aRow + r * 64] = va[r].w;
        }
#pragma unroll
        for (int r = 0; r < 2; r++)
            *(float4*)(&Bs[buf][(bRow + r * 8) * BN + bCol4 * 4]) = vb[r];
    };

    const int nst = (K + BK - 1) / BK;
    ldg(0); sts(0);
    __syncthreads();
    for (int s = 0; s < nst; s++) {
        const int buf = s & 1;
        if (s + 1 < nst) ldg((s + 1) * BK);
#pragma unroll
        for (int kk = 0; kk < BK; kk++) {
            ulonglong2 pa0 = *(const ulonglong2*)&As[buf][kk * BM + tr * TM];
            ulonglong2 pa1 = *(const ulonglong2*)&As[buf][kk * BM + tr * TM + 4];
            u64 ra2[TM / 2] = {pa0.x, pa0.y, pa1.x, pa1.y};
            float4 b0 = *(const float4*)&Bs[buf][kk * BN + tc * TN];
            float4 b1 = *(const float4*)&Bs[buf][kk * BN + tc * TN + 4];
            u64 rb2[TN];
            rb2[0] = pack2(b0.x, b0.x); rb2[1] = pack2(b0.y, b0.y);
            rb2[2] = pack2(b0.z, b0.z); rb2[3] = pack2(b0.w, b0.w);
            rb2[4] = pack2(b1.x, b1.x); rb2[5] = pack2(b1.y, b1.y);
            rb2[6] = pack2(b1.z, b1.z); rb2[7] = pack2(b1.w, b1.w);
#pragma unroll
            for (int i = 0; i < TM / 2; i++)
#pragma unroll
                for (int j = 0; j < TN; j++)
                    acc2[i][j] = ffma2(ra2[i], rb2[j], acc2[i][j]);
        }
        if (s + 1 < nst) { sts(buf ^ 1); __syncthreads(); }
    }

#pragma unroll
    for (int i2 = 0; i2 < TM / 2; i2++) {
        float2 f[TN];
#pragma unroll
        for (int j = 0; j < TN; j++) f[j] = *(float2*)&acc2[i2][j];
#pragma unroll
        for (int w = 0; w < 2; w++) {
            int row = row0 + tr * TM + 2 * i2 + w;
            if (row >= M) continue;
            int dn = 0, sn = 0;
            if (MODE == 1) { dn = rdst[row]; sn = rsrc[row]; }
            if (MODE == 2) { dn = rdst[row]; }
#pragma unroll
            for (int j = 0; j < TN; j += 4) {
                int col = col0 + tc * TN + j;
                if (col >= N) continue;
                float4 v;
                if (w == 0) v = make_float4(f[j].x, f[j+1].x, f[j+2].x, f[j+3].x);
                else        v = make_float4(f[j].y, f[j+1].y, f[j+2].y, f[j+3].y);
                if (bias) {
                    float4 bb = *(const float4*)(bias + col);
                    v.x += bb.x; v.y += bb.y; v.z += bb.z; v.w += bb.w;
                }
                if (MODE == 0) {
                    if (relu) {
                        v.x = fmaxf(v.x, 0.f); v.y = fmaxf(v.y, 0.f);
                        v.z = fmaxf(v.z, 0.f); v.w = fmaxf(v.w, 0.f);
                    }
                    *(float4*)(C + (size_t)row * ldc + col) = v;
                } else if (MODE == 1) {
                    float4 a4 = *(const float4*)(Pa + (size_t)dn * ldp + col);
                    float4 b4 = *(const float4*)(Pb + (size_t)sn * ldp + col);
                    v.x = fmaxf(v.x + a4.x + b4.x, 0.f);
                    v.y = fmaxf(v.y + a4.y + b4.y, 0.f);
                    v.z = fmaxf(v.z + a4.z + b4.z, 0.f);
                    v.w = fmaxf(v.w + a4.w + b4.w, 0.f);
                    *(float4*)(C + (size_t)row * ldc + col) = v;
                } else {
                    float* p = C + (size_t)dn * ldc + col;
                    atomicAdd(p + 0, v.x); atomicAdd(p + 1, v.y);
                    atomicAdd(p + 2, v.z); atomicAdd(p + 3, v.w);
                }
            }
        }
    }
}

__global__ void concat_k(const float* __restrict__ x, int nn) {
    int idx = blockIdx.x * blockDim.x + threadIdx.x;
    int n = idx >> 8, c = idx & 255;
    if (n < nn)
        g_u[idx] = (c < NF) ? x[n * NF + c] : g_aggr[n * MSGD + (c - NF)];
}
__global__ void pool_k(const float* __restrict__ h, int nn) {
    int idx = blockIdx.x * blockDim.x + threadIdx.x;
    int n = idx >> 7, c = idx & 127;
    if (n < nn) {
        int b = g_batch[n];
        atomicAdd(&g_pool[b * NHID + c], h[idx]);
        if (c == 0) atomicAdd(&g_cnt[b], 1.0f);
    }
}
__global__ void gmlp_k(const float* __restrict__ W1, const float* __restrict__ b1,
                       const float* __restrict__ W2, const float* __restrict__ b2,
                       const float* __restrict__ W3, const float* __restrict__ b3,
                       float* __restrict__ out) {
    int g = blockIdx.x, t = threadIdx.x;
    __shared__ float s_in[NHID], s_h[NHID];
    float c = fmaxf(g_cnt[g], 1.0f);
    s_in[t] = g_pool[g * NHID + t] / c;
    __syncthreads();
    float a = b1[t];
    for (int k = 0; k < NHID; k++) a += s_in[k] * W1[k * NHID + t];
    s_h[t] = fmaxf(a, 0.0f);
    __syncthreads();
    a = b2[t];
    for (int k = 0; k < NHID; k++) a += s_h[k] * W2[k * NHID + t];
    a = fmaxf(a, 0.0f);
    __syncthreads();
    s_in[t] = a * W3[t];
    __syncthreads();
    for (int s = 64; s > 0; s >>= 1) {
        if (t < s) s_in[t] += s_in[t + s];
        __syncthreads();
    }
    if (t == 0) out[g] = s_in[0] + b3[0];
}

// ---------------------------------------------------------------------------
// launch — edge1 on s2 (R13 pattern) + L3 on s3 overlapping L2[c+1].
// ---------------------------------------------------------------------------
extern "C" void kernel_launch(void* const* d_in, const int* in_sizes, int n_in,
                              void* d_out, int out_size) {
    const float* x       = (const float*)d_in[0];
    const int*   eidx    = (const int*)d_in[1];
    const float* eattr   = (const float*)d_in[2];
    const int*   batch   = (const int*)d_in[3];
    const float* msg_W1  = (const float*)d_in[4];
    const float* msg_b1  = (const float*)d_in[5];
    const float* msg_W2  = (const float*)d_in[6];
    const float* msg_b2  = (const float*)d_in[7];
    const float* msg_W3  = (const float*)d_in[8];
    const float* msg_b3  = (const float*)d_in[9];
    const float* node_W1 = (const float*)d_in[10];
    const float* node_b1 = (const float*)d_in[11];
    const float* node_W2 = (const float*)d_in[12];
    const float* node_b2 = (const float*)d_in[13];
    const float* node_W3 = (const float*)d_in[14];
    const float* node_b3 = (const float*)d_in[15];
    const float* glob_W1 = (const float*)d_in[16];
    const float* glob_b1 = (const float*)d_in[17];
    const float* glob_W2 = (const float*)d_in[18];
    const float* glob_b2 = (const float*)d_in[19];
    const float* glob_W3 = (const float*)d_in[20];
    const float* glob_b3 = (const float*)d_in[21];
    float* out = (float*)d_out;

    float *pPa, *pPb, *ph1a, *ph1b, *ph2a, *ph2b, *pag, *pu, *pn1, *pn2, *phn;
    int *psrc, *pdst;
    __nv_bfloat16 *paH,*paL,*pbH,*pbL,*w2H,*w2L,*w3H,*w3L,*n1H,*n1L,*n2H,*n2L,*n3H,*n3L;
    cudaGetSymbolAddress((void**)&pPa, g_Pa);
    cudaGetSymbolAddress((void**)&pPb, g_Pb);
    cudaGetSymbolAddress((void**)&ph1a, g_h1a);
    cudaGetSymbolAddress((void**)&ph1b, g_h1b);
    cudaGetSymbolAddress((void**)&ph2a, g_h2a);
    cudaGetSymbolAddress((void**)&ph2b, g_h2b);
    cudaGetSymbolAddress((void**)&pag, g_aggr);
    cudaGetSymbolAddress((void**)&pu, g_u);
    cudaGetSymbolAddress((void**)&pn1, g_n1);
    cudaGetSymbolAddress((void**)&pn2, g_n2);
    cudaGetSymbolAddress((void**)&phn, g_hn);
    cudaGetSymbolAddress((void**)&psrc, g_src);
    cudaGetSymbolAddress((void**)&pdst, g_dst);
    cudaGetSymbolAddress((void**)&paH, g_wpaH); cudaGetSymbolAddress((void**)&paL, g_wpaL);
    cudaGetSymbolAddress((void**)&pbH, g_wpbH); cudaGetSymbolAddress((void**)&pbL, g_wpbL);
    cudaGetSymbolAddress((void**)&w2H, g_w2H);  cudaGetSymbolAddress((void**)&w2L, g_w2L);
    cudaGetSymbolAddress((void**)&w3H, g_w3H);  cudaGetSymbolAddress((void**)&w3L, g_w3L);
    cudaGetSymbolAddress((void**)&n1H, g_n1H);  cudaGetSymbolAddress((void**)&n1L, g_n1L);
    cudaGetSymbolAddress((void**)&n2H, g_n2H);  cudaGetSymbolAddress((void**)&n2L, g_n2L);
    cudaGetSymbolAddress((void**)&n3H, g_n3H);  cudaGetSymbolAddress((void**)&n3L, g_n3L);

    cudaFuncSetAttribute(tmma_k<0>, cudaFuncAttributeMaxDynamicSharedMemorySize, TSMEM);
    cudaFuncSetAttribute(tmma_k<2>, cudaFuncAttributeMaxDynamicSharedMemorySize, TSMEM);

    static cudaStream_t s2 = nullptr, s3 = nullptr;
    static cudaEvent_t evPrep, evE[NCHUNK], evL2[NCHUNK], evL3[NCHUNK];
    if (!s2) {
        cudaStreamCreateWithFlags(&s2, cudaStreamNonBlocking);
        cudaStreamCreateWithFlags(&s3, cudaStreamNonBlocking);
        cudaEventCreateWithFlags(&evPrep, cudaEventDisableTiming);
        for (int i = 0; i < NCHUNK; i++) {
            cudaEventCreateWithFlags(&evE[i], cudaEventDisableTiming);
            cudaEventCreateWithFlags(&evL2[i], cudaEventDisableTiming);
            cudaEventCreateWithFlags(&evL3[i], cudaEventDisableTiming);
        }
    }

    const int NE = NEDGES, NN = NNODES;

    // launches 1-4 (so ncu -s 5 captures launch #6 = tmma Pb, a real GEMM)
    detect_k<<<1, 64>>>(eidx, batch, NN);
    convert_k<<<(NE + 255) / 256, 256>>>(eidx, batch, NE, NN);
    zero_k<<<4096, 256>>>();
    {
        WPArgs wa;
        wa.e[0] = {msg_W1,           paH, paL, 128, 300, 300, 128};
        wa.e[1] = {msg_W1 + 128*300, pbH, pbL, 128, 300, 300, 128};
        wa.e[2] = {msg_W2,           w2H, w2L, 300, 300, 300, 320};
        wa.e[3] = {msg_W3,           w3H, w3L, 300, 128, 128, 320};
        wa.e[4] = {node_W1,          n1H, n1L, 256, 300, 300, 256};
        wa.e[5] = {node_W2,          n2H, n2L, 300, 300, 300, 320};
        wa.e[6] = {node_W3,          n3H, n3L, 300, 128, 128, 320};
        wprep_all<<<dim3((300*320 + 255)/256, 7), 256>>>(wa);
    }

    const int MT_N = (NN + 127) / 128;
    const int MT_E = (ECHUNK + 127) / 128;

    // launches 5,6: Pa/Pb projections (tensor) — #6 is what ncu profiles
    tmma_k<0><<<dim3(5, MT_N), 256, TSMEM>>>(NN, HID, NF, x, NF,
        paH, paL, 128, msg_b1, pPa, HID, 0, nullptr);
    tmma_k<0><<<dim3(5, MT_N), 256, TSMEM>>>(NN, HID, NF, x, NF,
        pbH, pbL, 128, nullptr, pPb, HID, 0, nullptr);
    cudaEventRecord(evPrep, 0);
    cudaStreamWaitEvent(s2, evPrep, 0);

    float* h1buf[2] = {ph1a, ph1b};
    float* h2buf[2] = {ph2a, ph2b};
    for (int c = 0; c < NCHUNK; c++) {
        const int e0 = c * ECHUNK;
        const int Mc = ECHUNK;
        float* ph1 = h1buf[c & 1];
        float* ph2 = h2buf[c & 1];

        // edge1 on s2 (FMA pipe)
        if (c >= 2) cudaStreamWaitEvent(s2, evL2[c - 2], 0);
        sgemm_k<1><<<dim3((Mc + BM - 1)/BM, (HID + BN - 1)/BN), 256, 0, s2>>>(
            Mc, HID, EF, eattr + (size_t)e0 * EF, EF,
            msg_W1 + (size_t)(2 * NF) * HID, HID, nullptr, ph1, HID, 1,
            pdst + e0, psrc + e0, pPa, pPb, HID);
        cudaEventRecord(evE[c], s2);

        // L2 on main (tensor pipe); h2 buffer reuse gated by L3[c-2]
        cudaStreamWaitEvent(0, evE[c], 0);
        if (c >= 2) cudaStreamWaitEvent(0, evL3[c - 2], 0);
        tmma_k<0><<<dim3(5, MT_E), 256, TSMEM>>>(Mc, HID, HID,
            ph1, HID, w2H, w2L, 320, msg_b2, ph2, HID, 1, nullptr);
        cudaEventRecord(evL2[c], 0);

        // L3 on s3 (atomics-heavy) — overlaps L2[c+1]
        cudaStreamWaitEvent(s3, evL2[c], 0);
        tmma_k<2><<<dim3(2, MT_E), 256, TSMEM, s3>>>(Mc, MSGD, HID,
            ph2, HID, w3H, w3L, 320, msg_b3, pag, MSGD, 0, pdst + e0);
        cudaEventRecord(evL3[c], s3);
    }

    // node MLP (main stream) — needs aggr complete (L3s serialized on s3)
    cudaStreamWaitEvent(0, evL3[NCHUNK - 1], 0);
    concat_k<<<(NN * 256 + 255) / 256, 256>>>(x, NN);
    tmma_k<0><<<dim3(5, MT_N), 256, TSMEM>>>(NN, HID, NF + MSGD, pu, NF + MSGD,
        n1H, n1L, 256, node_b1, pn1, HID, 1, nullptr);
    tmma_k<0><<<dim3(5, MT_N), 256, TSMEM>>>(NN, HID, HID, pn1, HID,
        n2H, n2L, 320, node_b2, pn2, HID, 1, nullptr);
    tmma_k<0><<<dim3(2, MT_N), 256, TSMEM>>>(NN, NHID, HID, pn2, HID,
        n3H, n3L, 320, node_b3, phn, NHID, 0, nullptr);

    pool_k<<<(NN * NHID + 255) / 256, 256>>>(phn, NN);
    gmlp_k<<<NGRAPH, NHID>>>(glob_W1, glob_b1, glob_W2, glob_b2,
                             glob_W3, glob_b3, out);
}

// round 17
// speedup vs baseline: 1.1591x; 1.1080x over previous
#include <cuda_runtime.h>
#include <cuda_bf16.h>
#include <cuda_fp16.h>
#include <cstdint>

#define NNODES 50000
#define NEDGES 800000
#define NF     128
#define EF     32
#define HID    300
#define MSGD   128
#define NHID   128
#define NGRAPH 64

#define ECHUNK 200000
#define NCHUNK (NEDGES / ECHUNK)

typedef unsigned long long u64;

// ---------------------------------------------------------------------------
// Scratch (__device__ globals; total ~1.31GB, < 2GB for GOTPCREL safety)
// ---------------------------------------------------------------------------
__device__ float g_Pa[NNODES * HID];
__device__ float g_Pb[NNODES * HID];
__device__ float g_h1a[(size_t)ECHUNK * HID];
__device__ float g_h1b[(size_t)ECHUNK * HID];
__device__ float g_h2a[(size_t)ECHUNK * HID];
__device__ float g_h2b[(size_t)ECHUNK * HID];
__device__ float g_aggr[NNODES * MSGD];
__device__ float g_u[NNODES * (NF + MSGD)];
__device__ float g_n1[NNODES * HID];
__device__ float g_n2[NNODES * HID];
__device__ float g_hn[NNODES * NHID];
__device__ float g_pool[NGRAPH * NHID];
__device__ float g_cnt[NGRAPH];
__device__ int   g_src[NEDGES];
__device__ int   g_dst[NEDGES];
__device__ int   g_batch[NNODES];
__device__ int   g_e64;
__device__ int   g_b64;

// split-transposed weights: Wt[n][kpad], 16-bit hi/lo (bf16 or fp16 bits)
__device__ __nv_bfloat16 g_wpaH[300*128], g_wpaL[300*128];
__device__ __nv_bfloat16 g_wpbH[300*128], g_wpbL[300*128];
__device__ __nv_bfloat16 g_w2H [300*320], g_w2L [300*320];   // fp16 bits (L2)
__device__ __nv_bfloat16 g_w3H [128*320], g_w3L [128*320];   // fp16 bits (L3)
__device__ __nv_bfloat16 g_n1H [300*256], g_n1L [300*256];
__device__ __nv_bfloat16 g_n2H [300*320], g_n2L [300*320];
__device__ __nv_bfloat16 g_n3H [128*320], g_n3L [128*320];

// ---------------------------------------------------------------------------
// PTX helpers (sm_80-compatible)
// ---------------------------------------------------------------------------
__device__ __forceinline__ uint32_t smem_u32(const void* p) {
    uint32_t a;
    asm("{ .reg .u64 t; cvta.to.shared.u64 t, %1; cvt.u32.u64 %0, t; }"
        : "=r"(a) : "l"(p));
    return a;
}
__device__ __forceinline__ void ldm_x4(uint32_t* r, uint32_t addr) {
    asm volatile("ldmatrix.sync.aligned.m8n8.x4.shared.b16 {%0,%1,%2,%3}, [%4];"
        : "=r"(r[0]), "=r"(r[1]), "=r"(r[2]), "=r"(r[3]) : "r"(addr));
}
__device__ __forceinline__ void mma_bf16(float* c, const uint32_t* a,
                                         const uint32_t* b) {
    asm volatile(
        "mma.sync.aligned.m16n8k16.row.col.f32.bf16.bf16.f32 "
        "{%0,%1,%2,%3}, {%4,%5,%6,%7}, {%8,%9}, {%0,%1,%2,%3};"
        : "+f"(c[0]), "+f"(c[1]), "+f"(c[2]), "+f"(c[3])
        : "r"(a[0]), "r"(a[1]), "r"(a[2]), "r"(a[3]), "r"(b[0]), "r"(b[1]));
}
__device__ __forceinline__ void mma_f16(float* c, const uint32_t* a,
                                        const uint32_t* b) {
    asm volatile(
        "mma.sync.aligned.m16n8k16.row.col.f32.f16.f16.f32 "
        "{%0,%1,%2,%3}, {%4,%5,%6,%7}, {%8,%9}, {%0,%1,%2,%3};"
        : "+f"(c[0]), "+f"(c[1]), "+f"(c[2]), "+f"(c[3])
        : "r"(a[0]), "r"(a[1]), "r"(a[2]), "r"(a[3]), "r"(b[0]), "r"(b[1]));
}

// ---------------------------------------------------------------------------
// small kernels
// ---------------------------------------------------------------------------
__global__ void detect_k(const int* __restrict__ e, const int* __restrict__ b, int nn) {
    __shared__ int se, sb;
    int t = threadIdx.x;
    if (t == 0) { se = 1; sb = 1; }
    __syncthreads();
    if (e[2 * t + 1] != 0) se = 0;
    int w = nn - 1 - 2 * t;
    if (b[w] != 0) sb = 0;
    __syncthreads();
    if (t == 0) { g_e64 = se; g_b64 = sb; }
}
__global__ void convert_k(const int* __restrict__ e, const int* __restrict__ b,
                          int ne, int nn) {
    int i = blockIdx.x * blockDim.x + threadIdx.x;
    int e64 = g_e64, b64 = g_b64;
    if (i < ne) {
        if (e64) { g_src[i] = e[2 * i]; g_dst[i] = e[2 * (ne + i)]; }
        else     { g_src[i] = e[i];     g_dst[i] = e[ne + i]; }
    }
    if (i < nn) g_batch[i] = b64 ? b[2 * i] : b[i];
}
__global__ void zero_k() {
    long i = blockIdx.x * (long)blockDim.x + threadIdx.x;
    long stride = gridDim.x * (long)blockDim.x;
    for (long j = i; j < (long)NNODES * MSGD; j += stride) g_aggr[j] = 0.0f;
    if (i < NGRAPH * NHID) g_pool[i] = 0.0f;
    if (i < NGRAPH) g_cnt[i] = 0.0f;
}
// batched weight split+transpose; h16=1 -> fp16 hi/lo bits, else bf16
struct WPEnt {
    const float* W;
    __nv_bfloat16* hi;
    __nv_bfloat16* lo;
    int K, Nw, ldw, kpad, h16;
};
struct WPArgs { WPEnt e[7]; };
__global__ void wprep_all(WPArgs a) {
    const WPEnt& w = a.e[blockIdx.y];
    int idx = blockIdx.x * blockDim.x + threadIdx.x;
    if (idx >= w.Nw * w.kpad) return;
    int n = idx / w.kpad, k = idx % w.kpad;
    float v = (k < w.K) ? w.W[(size_t)k * w.ldw + n] : 0.0f;
    if (w.h16) {
        __half h = __float2half(v);
        ((uint16_t*)w.hi)[idx] = __half_as_ushort(h);
        ((uint16_t*)w.lo)[idx] = __half_as_ushort(__float2half(v - __half2float(h)));
    } else {
        __nv_bfloat16 h = __float2bfloat16(v);
        w.hi[idx] = h;
        w.lo[idx] = __float2bfloat16(v - __bfloat162float(h));
    }
}

// ---------------------------------------------------------------------------
// Tensor GEMM via mma.sync split.
// SPLIT=3: bf16, A=ah+al, 3 products (hi*hi + hi*lo + lo*hi), err ~2^-16
// SPLIT=2: fp16, A=ah only, B=bh+bl, 2 products (ah*bh + ah*bl = ah*B),
//          err = (A-fp16(A))*B ~ 2^-12  -> fewer ldm AND fewer MMAs
// CTA 128x64, BK=32, 256 thr (8 warps 4m x 2n, warp 32x32).
// MODE 0: C = (relu?)(acc+bias)   MODE 2: atomicAdd(C[rdst[row]], acc+bias)
// ---------------------------------------------------------------------------
#define RSB 80
#define OF_AH 0
#define OF_AL 10240
#define OF_BH 20480
#define OF_BL 25600
#define TBUF  30720
#define TSMEM (2*TBUF)

template <int MODE, int SPLIT>
__global__ void __launch_bounds__(256, 2)
tmma_k(int M, int N, int K,
       const float* __restrict__ A, int lda,
       const __nv_bfloat16* __restrict__ BH, const __nv_bfloat16* __restrict__ BL,
       int kpad,
       const float* __restrict__ bias,
       float* __restrict__ C, int ldc, int relu,
       const int* __restrict__ rdst) {
    extern __shared__ char sm[];
    const uint32_t smb = smem_u32(sm);
    const int tid = threadIdx.x;
    const int lane = tid & 31;
    const int wid = tid >> 5;
    const int wm = wid & 3, wn = wid >> 2;
    const int col0 = blockIdx.x * 64;
    const int row0 = blockIdx.y * 128;

    float cc[2][4][4];
#pragma unroll
    for (int a = 0; a < 2; a++)
#pragma unroll
        for (int b = 0; b < 4; b++)
#pragma unroll
            for (int c = 0; c < 4; c++) cc[a][b][c] = 0.0f;

    float4 va[4];
    uint4 vbh, vbl;

    const int rowA = tid >> 1, halfA = tid & 1;
    const int nB = tid >> 2, segB = tid & 3;

    auto ldgA = [&](int k0) {
        int grow = row0 + rowA;
        const float* p = A + (size_t)grow * lda + k0 + halfA * 16;
        if (grow < M && k0 + halfA * 16 + 16 <= K) {
            va[0] = ((const float4*)p)[0]; va[1] = ((const float4*)p)[1];
            va[2] = ((const float4*)p)[2]; va[3] = ((const float4*)p)[3];
        } else {
            float* vf = (float*)va;
#pragma unroll
            for (int j = 0; j < 16; j++) {
                int gk = k0 + halfA * 16 + j;
                vf[j] = (grow < M && gk < K) ? p[j] : 0.0f;
            }
        }
    };
    auto ldgB = [&](int k0) {
        if (col0 + nB < N) {
            vbh = *(const uint4*)(BH + (size_t)(col0 + nB) * kpad + k0 + segB * 8);
            vbl = *(const uint4*)(BL + (size_t)(col0 + nB) * kpad + k0 + segB * 8);
        } else {
            vbh = make_uint4(0, 0, 0, 0);
            vbl = make_uint4(0, 0, 0, 0);
        }
    };
    auto sts = [&](int buf) {
        const float* vf = (const float*)va;
        if (SPLIT == 3) {
            uint32_t hw[8], lw[8];
#pragma unroll
            for (int j = 0; j < 8; j++) {
                float v0 = vf[2 * j], v1 = vf[2 * j + 1];
                __nv_bfloat16 h0 = __float2bfloat16(v0), h1 = __float2bfloat16(v1);
                __nv_bfloat16 l0 = __float2bfloat16(v0 - __bfloat162float(h0));
                __nv_bfloat16 l1 = __float2bfloat16(v1 - __bfloat162float(h1));
                hw[j] = (uint32_t)__bfloat16_as_ushort(h0) |
                        ((uint32_t)__bfloat16_as_ushort(h1) << 16);
                lw[j] = (uint32_t)__bfloat16_as_ushort(l0) |
                        ((uint32_t)__bfloat16_as_ushort(l1) << 16);
            }
            char* ba = sm + buf + OF_AH + rowA * RSB + halfA * 32;
            *(uint4*)(ba +  0) = make_uint4(hw[0], hw[1], hw[2], hw[3]);
            *(uint4*)(ba + 16) = make_uint4(hw[4], hw[5], hw[6], hw[7]);
            char* bl_ = sm + buf + OF_AL + rowA * RSB + halfA * 32;
            *(uint4*)(bl_ +  0) = make_uint4(lw[0], lw[1], lw[2], lw[3]);
            *(uint4*)(bl_ + 16) = make_uint4(lw[4], lw[5], lw[6], lw[7]);
        } else {
            uint32_t hw[8];
#pragma unroll
            for (int j = 0; j < 8; j++) {
                __half2 h2 = __floats2half2_rn(vf[2 * j], vf[2 * j + 1]);
                hw[j] = *(uint32_t*)&h2;
            }
            char* ba = sm + buf + OF_AH + rowA * RSB + halfA * 32;
            *(uint4*)(ba +  0) = make_uint4(hw[0], hw[1], hw[2], hw[3]);
            *(uint4*)(ba + 16) = make_uint4(hw[4], hw[5], hw[6], hw[7]);
        }
        *(uint4*)(sm + buf + OF_BH + nB * RSB + segB * 16) = vbh;
        *(uint4*)(sm + buf + OF_BL + nB * RSB + segB * 16) = vbl;
    };
    auto compute = [&](int buf) {
#pragma unroll
        for (int k16 = 0; k16 < 32; k16 += 16) {
            uint32_t ah[2][4], al[2][4], bh[4][2], bl2[4][2];
#pragma unroll
            for (int mt = 0; mt < 2; mt++) {
                uint32_t ad = smb + buf + OF_AH
                    + (uint32_t)(wm * 32 + mt * 16 + (lane & 15)) * RSB
                    + (uint32_t)(k16 + (lane >> 4) * 8) * 2;
                ldm_x4(ah[mt], ad);
                if (SPLIT == 3) ldm_x4(al[mt], ad + (OF_AL - OF_AH));
            }
            {
                int g = lane >> 3, r = lane & 7;
#pragma unroll
                for (int np = 0; np < 2; np++) {
                    uint32_t bd = smb + buf + OF_BH
                        + (uint32_t)(wn * 32 + np * 16 + ((g >> 1) & 1) * 8 + r) * RSB
                        + (uint32_t)(k16 + (g & 1) * 8) * 2;
                    uint32_t t4[4];
                    ldm_x4(t4, bd);
                    bh[np * 2][0] = t4[0]; bh[np * 2][1] = t4[1];
                    bh[np * 2 + 1][0] = t4[2]; bh[np * 2 + 1][1] = t4[3];
                    ldm_x4(t4, bd + (OF_BL - OF_BH));
                    bl2[np * 2][0] = t4[0]; bl2[np * 2][1] = t4[1];
                    bl2[np * 2 + 1][0] = t4[2]; bl2[np * 2 + 1][1] = t4[3];
                }
            }
#pragma unroll
            for (int mt = 0; mt < 2; mt++)
#pragma unroll
                for (int nt = 0; nt < 4; nt++) {
                    if (SPLIT == 3) {
                        mma_bf16(cc[mt][nt], ah[mt], bh[nt]);
                        mma_bf16(cc[mt][nt], ah[mt], bl2[nt]);
                        mma_bf16(cc[mt][nt], al[mt], bh[nt]);
                    } else {
                        mma_f16(cc[mt][nt], ah[mt], bh[nt]);
                        mma_f16(cc[mt][nt], ah[mt], bl2[nt]);
                    }
                }
        }
    };

    const int nst = (K + 31) / 32;
    ldgA(0); ldgB(0);
    sts(0);
    __syncthreads();
    for (int s = 0; s < nst; s++) {
        const int buf = (s & 1) * TBUF;
        if (s + 1 < nst) { ldgA((s + 1) * 32); ldgB((s + 1) * 32); }
        compute(buf);
        if (s + 1 < nst) {
            sts(((s + 1) & 1) * TBUF);
            __syncthreads();
        }
    }

#pragma unroll
    for (int mt = 0; mt < 2; mt++) {
#pragma unroll
        for (int h = 0; h < 2; h++) {
            int row = row0 + wm * 32 + mt * 16 + (lane >> 2) + h * 8;
            if (row >= M) continue;
            int dn = (MODE == 2) ? rdst[row] : 0;
#pragma unroll
            for (int nt = 0; nt < 4; nt++) {
                int col = col0 + wn * 32 + nt * 8 + (lane & 3) * 2;
                if (col >= N) continue;
                float v0 = cc[mt][nt][h * 2], v1 = cc[mt][nt][h * 2 + 1];
                if (bias) {
                    float2 bb = *(const float2*)(bias + col);
                    v0 += bb.x; v1 += bb.y;
                }
                if (MODE == 0) {
                    if (relu) { v0 = fmaxf(v0, 0.f); v1 = fmaxf(v1, 0.f); }
                    *(float2*)(C + (size_t)row * ldc + col) = make_float2(v0, v1);
                } else {
                    atomicAdd(C + (size_t)dn * ldc + col, v0);
                    atomicAdd(C + (size_t)dn * ldc + col + 1, v1);
                }
            }
        }
    }
}

// ---------------------------------------------------------------------------
// SIMT FFMA2 SGEMM — MODE 1 (edge layer-1 gather epilogue, K=32)  [R9 proven]
// ---------------------------------------------------------------------------
#define BM 128
#define BN 128
#define BK 16
#define TM 8
#define TN 8
__device__ __forceinline__ u64 ffma2(u64 a, u64 b, u64 c) {
    u64 d;
    asm("fma.rn.f32x2 %0, %1, %2, %3;" : "=l"(d) : "l"(a), "l"(b), "l"(c));
    return d;
}
__device__ __forceinline__ u64 pack2(float lo, float hi) {
    u64 d;
    asm("mov.b64 %0, {%1, %2};" : "=l"(d) : "f"(lo), "f"(hi));
    return d;
}

template <int MODE>
__global__ void __launch_bounds__(256, 2)
sgemm_k(int M, int N, int K,
        const float* __restrict__ A, int lda,
        const float* __restrict__ B, int ldb,
        const float* __restrict__ bias,
        float* __restrict__ C, int ldc,
        int relu,
        const int* __restrict__ rdst, const int* __restrict__ rsrc,
        const float* __restrict__ Pa, const float* __restrict__ Pb, int ldp) {
    __shared__ float As[2][BK * BM];
    __shared__ float Bs[2][BK * BN];
    const int row0 = blockIdx.x * BM;
    const int col0 = blockIdx.y * BN;
    const int tid = threadIdx.x;
    const int tr = tid / (BN / TN);
    const int tc = tid % (BN / TN);
    const int aRow = tid / (BK / 4), aCol4 = tid % (BK / 4);
    const int bRow = tid / (BN / 4), bCol4 = tid % (BN / 4);

    u64 acc2[TM / 2][TN];
#pragma unroll
    for (int i = 0; i < TM / 2; i++)
#pragma unroll
        for (int j = 0; j < TN; j++) acc2[i][j] = 0ull;

    float4 va[2], vb[2];
    auto ldg = [&](int k0) {
#pragma unroll
        for (int r = 0; r < 2; r++) {
            int grow = row0 + aRow + r * 64, gk = k0 + aCol4 * 4;
            va[r] = make_float4(0.f, 0.f, 0.f, 0.f);
            if (grow < M && gk < K)
                va[r] = *(const float4*)(A + (size_t)grow * lda + gk);
        }
#pragma unroll
        for (int r = 0; r < 2; r++) {
            int gk = k0 + bRow + r * 8, gcol = col0 + bCol4 * 4;
            vb[r] = make_float4(0.f, 0.f, 0.f, 0.f);
            if (gk < K && gcol < N)
                vb[r] = *(const float4*)(B + (size_t)gk * ldb + gcol);
        }
    };
    auto sts = [&](int buf) {
#pragma unroll
        for (int r = 0; r < 2; r++) {
            As[buf][(aCol4 * 4 + 0) * BM + aRow + r * 64] = va[r].x;
            As[buf][(aCol4 * 4 + 1) * BM + aRow + r * 64] = va[r].y;
            As[buf][(aCol4 * 4 + 2) * BM + aRow + r * 64] = va[r].z;
            As[buf][(aCol4 * 4 + 3) * BM + aRow + r * 64] = va[r].w;
        }
#pragma unroll
        for (int r = 0; r < 2; r++)
            *(float4*)(&Bs[buf][(bRow + r * 8) * BN + bCol4 * 4]) = vb[r];
    };

    const int nst = (K + BK - 1) / BK;
    ldg(0); sts(0);
    __syncthreads();
    for (int s = 0; s < nst; s++) {
        const int buf = s & 1;
        if (s + 1 < nst) ldg((s + 1) * BK);
#pragma unroll
        for (int kk = 0; kk < BK; kk++) {
            ulonglong2 pa0 = *(const ulonglong2*)&As[buf][kk * BM + tr * TM];
            ulonglong2 pa1 = *(const ulonglong2*)&As[buf][kk * BM + tr * TM + 4];
            u64 ra2[TM / 2] = {pa0.x, pa0.y, pa1.x, pa1.y};
            float4 b0 = *(const float4*)&Bs[buf][kk * BN + tc * TN];
            float4 b1 = *(const float4*)&Bs[buf][kk * BN + tc * TN + 4];
            u64 rb2[TN];
            rb2[0] = pack2(b0.x, b0.x); rb2[1] = pack2(b0.y, b0.y);
            rb2[2] = pack2(b0.z, b0.z); rb2[3] = pack2(b0.w, b0.w);
            rb2[4] = pack2(b1.x, b1.x); rb2[5] = pack2(b1.y, b1.y);
            rb2[6] = pack2(b1.z, b1.z); rb2[7] = pack2(b1.w, b1.w);
#pragma unroll
            for (int i = 0; i < TM / 2; i++)
#pragma unroll
                for (int j = 0; j < TN; j++)
                    acc2[i][j] = ffma2(ra2[i], rb2[j], acc2[i][j]);
        }
        if (s + 1 < nst) { sts(buf ^ 1); __syncthreads(); }
    }

#pragma unroll
    for (int i2 = 0; i2 < TM / 2; i2++) {
        float2 f[TN];
#pragma unroll
        for (int j = 0; j < TN; j++) f[j] = *(float2*)&acc2[i2][j];
#pragma unroll
        for (int w = 0; w < 2; w++) {
            int row = row0 + tr * TM + 2 * i2 + w;
            if (row >= M) continue;
            int dn = 0, sn = 0;
            if (MODE == 1) { dn = rdst[row]; sn = rsrc[row]; }
            if (MODE == 2) { dn = rdst[row]; }
#pragma unroll
            for (int j = 0; j < TN; j += 4) {
                int col = col0 + tc * TN + j;
                if (col >= N) continue;
                float4 v;
                if (w == 0) v = make_float4(f[j].x, f[j+1].x, f[j+2].x, f[j+3].x);
                else        v = make_float4(f[j].y, f[j+1].y, f[j+2].y, f[j+3].y);
                if (bias) {
                    float4 bb = *(const float4*)(bias + col);
                    v.x += bb.x; v.y += bb.y; v.z += bb.z; v.w += bb.w;
                }
                if (MODE == 0) {
                    if (relu) {
                        v.x = fmaxf(v.x, 0.f); v.y = fmaxf(v.y, 0.f);
                        v.z = fmaxf(v.z, 0.f); v.w = fmaxf(v.w, 0.f);
                    }
                    *(float4*)(C + (size_t)row * ldc + col) = v;
                } else if (MODE == 1) {
                    float4 a4 = *(const float4*)(Pa + (size_t)dn * ldp + col);
                    float4 b4 = *(const float4*)(Pb + (size_t)sn * ldp + col);
                    v.x = fmaxf(v.x + a4.x + b4.x, 0.f);
                    v.y = fmaxf(v.y + a4.y + b4.y, 0.f);
                    v.z = fmaxf(v.z + a4.z + b4.z, 0.f);
                    v.w = fmaxf(v.w + a4.w + b4.w, 0.f);
                    *(float4*)(C + (size_t)row * ldc + col) = v;
                } else {
                    float* p = C + (size_t)dn * ldc + col;
                    atomicAdd(p + 0, v.x); atomicAdd(p + 1, v.y);
                    atomicAdd(p + 2, v.z); atomicAdd(p + 3, v.w);
                }
            }
        }
    }
}

__global__ void concat_k(const float* __restrict__ x, int nn) {
    int idx = blockIdx.x * blockDim.x + threadIdx.x;
    int n = idx >> 8, c = idx & 255;
    if (n < nn)
        g_u[idx] = (c < NF) ? x[n * NF + c] : g_aggr[n * MSGD + (c - NF)];
}
__global__ void pool_k(const float* __restrict__ h, int nn) {
    int idx = blockIdx.x * blockDim.x + threadIdx.x;
    int n = idx >> 7, c = idx & 127;
    if (n < nn) {
        int b = g_batch[n];
        atomicAdd(&g_pool[b * NHID + c], h[idx]);
        if (c == 0) atomicAdd(&g_cnt[b], 1.0f);
    }
}
__global__ void gmlp_k(const float* __restrict__ W1, const float* __restrict__ b1,
                       const float* __restrict__ W2, const float* __restrict__ b2,
                       const float* __restrict__ W3, const float* __restrict__ b3,
                       float* __restrict__ out) {
    int g = blockIdx.x, t = threadIdx.x;
    __shared__ float s_in[NHID], s_h[NHID];
    float c = fmaxf(g_cnt[g], 1.0f);
    s_in[t] = g_pool[g * NHID + t] / c;
    __syncthreads();
    float a = b1[t];
    for (int k = 0; k < NHID; k++) a += s_in[k] * W1[k * NHID + t];
    s_h[t] = fmaxf(a, 0.0f);
    __syncthreads();
    a = b2[t];
    for (int k = 0; k < NHID; k++) a += s_h[k] * W2[k * NHID + t];
    a = fmaxf(a, 0.0f);
    __syncthreads();
    s_in[t] = a * W3[t];
    __syncthreads();
    for (int s = 64; s > 0; s >>= 1) {
        if (t < s) s_in[t] += s_in[t + s];
        __syncthreads();
    }
    if (t == 0) out[g] = s_in[0] + b3[0];
}

// ---------------------------------------------------------------------------
// launch — R15 stream structure; L2/L3 use SPLIT=2 fp16 path.
// ---------------------------------------------------------------------------
extern "C" void kernel_launch(void* const* d_in, const int* in_sizes, int n_in,
                              void* d_out, int out_size) {
    const float* x       = (const float*)d_in[0];
    const int*   eidx    = (const int*)d_in[1];
    const float* eattr   = (const float*)d_in[2];
    const int*   batch   = (const int*)d_in[3];
    const float* msg_W1  = (const float*)d_in[4];
    const float* msg_b1  = (const float*)d_in[5];
    const float* msg_W2  = (const float*)d_in[6];
    const float* msg_b2  = (const float*)d_in[7];
    const float* msg_W3  = (const float*)d_in[8];
    const float* msg_b3  = (const float*)d_in[9];
    const float* node_W1 = (const float*)d_in[10];
    const float* node_b1 = (const float*)d_in[11];
    const float* node_W2 = (const float*)d_in[12];
    const float* node_b2 = (const float*)d_in[13];
    const float* node_W3 = (const float*)d_in[14];
    const float* node_b3 = (const float*)d_in[15];
    const float* glob_W1 = (const float*)d_in[16];
    const float* glob_b1 = (const float*)d_in[17];
    const float* glob_W2 = (const float*)d_in[18];
    const float* glob_b2 = (const float*)d_in[19];
    const float* glob_W3 = (const float*)d_in[20];
    const float* glob_b3 = (const float*)d_in[21];
    float* out = (float*)d_out;

    float *pPa, *pPb, *ph1a, *ph1b, *ph2a, *ph2b, *pag, *pu, *pn1, *pn2, *phn;
    int *psrc, *pdst;
    __nv_bfloat16 *paH,*paL,*pbH,*pbL,*w2H,*w2L,*w3H,*w3L,*n1H,*n1L,*n2H,*n2L,*n3H,*n3L;
    cudaGetSymbolAddress((void**)&pPa, g_Pa);
    cudaGetSymbolAddress((void**)&pPb, g_Pb);
    cudaGetSymbolAddress((void**)&ph1a, g_h1a);
    cudaGetSymbolAddress((void**)&ph1b, g_h1b);
    cudaGetSymbolAddress((void**)&ph2a, g_h2a);
    cudaGetSymbolAddress((void**)&ph2b, g_h2b);
    cudaGetSymbolAddress((void**)&pag, g_aggr);
    cudaGetSymbolAddress((void**)&pu, g_u);
    cudaGetSymbolAddress((void**)&pn1, g_n1);
    cudaGetSymbolAddress((void**)&pn2, g_n2);
    cudaGetSymbolAddress((void**)&phn, g_hn);
    cudaGetSymbolAddress((void**)&psrc, g_src);
    cudaGetSymbolAddress((void**)&pdst, g_dst);
    cudaGetSymbolAddress((void**)&paH, g_wpaH); cudaGetSymbolAddress((void**)&paL, g_wpaL);
    cudaGetSymbolAddress((void**)&pbH, g_wpbH); cudaGetSymbolAddress((void**)&pbL, g_wpbL);
    cudaGetSymbolAddress((void**)&w2H, g_w2H);  cudaGetSymbolAddress((void**)&w2L, g_w2L);
    cudaGetSymbolAddress((void**)&w3H, g_w3H);  cudaGetSymbolAddress((void**)&w3L, g_w3L);
    cudaGetSymbolAddress((void**)&n1H, g_n1H);  cudaGetSymbolAddress((void**)&n1L, g_n1L);
    cudaGetSymbolAddress((void**)&n2H, g_n2H);  cudaGetSymbolAddress((void**)&n2L, g_n2L);
    cudaGetSymbolAddress((void**)&n3H, g_n3H);  cudaGetSymbolAddress((void**)&n3L, g_n3L);

    cudaFuncSetAttribute(tmma_k<0,3>, cudaFuncAttributeMaxDynamicSharedMemorySize, TSMEM);
    cudaFuncSetAttribute(tmma_k<0,2>, cudaFuncAttributeMaxDynamicSharedMemorySize, TSMEM);
    cudaFuncSetAttribute(tmma_k<2,2>, cudaFuncAttributeMaxDynamicSharedMemorySize, TSMEM);

    static cudaStream_t s2 = nullptr, s3 = nullptr;
    static cudaEvent_t evPrep, evE[NCHUNK], evL2[NCHUNK], evL3[NCHUNK];
    if (!s2) {
        cudaStreamCreateWithFlags(&s2, cudaStreamNonBlocking);
        cudaStreamCreateWithFlags(&s3, cudaStreamNonBlocking);
        cudaEventCreateWithFlags(&evPrep, cudaEventDisableTiming);
        for (int i = 0; i < NCHUNK; i++) {
            cudaEventCreateWithFlags(&evE[i], cudaEventDisableTiming);
            cudaEventCreateWithFlags(&evL2[i], cudaEventDisableTiming);
            cudaEventCreateWithFlags(&evL3[i], cudaEventDisableTiming);
        }
    }

    const int NE = NEDGES, NN = NNODES;

    detect_k<<<1, 64>>>(eidx, batch, NN);
    convert_k<<<(NE + 255) / 256, 256>>>(eidx, batch, NE, NN);
    zero_k<<<4096, 256>>>();
    {
        WPArgs wa;
        wa.e[0] = {msg_W1,           paH, paL, 128, 300, 300, 128, 0};
        wa.e[1] = {msg_W1 + 128*300, pbH, pbL, 128, 300, 300, 128, 0};
        wa.e[2] = {msg_W2,           w2H, w2L, 300, 300, 300, 320, 1};  // fp16 (L2)
        wa.e[3] = {msg_W3,           w3H, w3L, 300, 128, 128, 320, 1};  // fp16 (L3)
        wa.e[4] = {node_W1,          n1H, n1L, 256, 300, 300, 256, 0};
        wa.e[5] = {node_W2,          n2H, n2L, 300, 300, 300, 320, 0};
        wa.e[6] = {node_W3,          n3H, n3L, 300, 128, 128, 320, 0};
        wprep_all<<<dim3((300*320 + 255)/256, 7), 256>>>(wa);
    }

    const int MT_N = (NN + 127) / 128;
    const int MT_E = (ECHUNK + 127) / 128;

    // Pa/Pb projections (bf16 3-product)
    tmma_k<0,3><<<dim3(5, MT_N), 256, TSMEM>>>(NN, HID, NF, x, NF,
        paH, paL, 128, msg_b1, pPa, HID, 0, nullptr);
    tmma_k<0,3><<<dim3(5, MT_N), 256, TSMEM>>>(NN, HID, NF, x, NF,
        pbH, pbL, 128, nullptr, pPb, HID, 0, nullptr);
    cudaEventRecord(evPrep, 0);
    cudaStreamWaitEvent(s2, evPrep, 0);

    float* h1buf[2] = {ph1a, ph1b};
    float* h2buf[2] = {ph2a, ph2b};
    for (int c = 0; c < NCHUNK; c++) {
        const int e0 = c * ECHUNK;
        const int Mc = ECHUNK;
        float* ph1 = h1buf[c & 1];
        float* ph2 = h2buf[c & 1];

        // edge1 on s2 (FMA pipe)
        if (c >= 2) cudaStreamWaitEvent(s2, evL2[c - 2], 0);
        sgemm_k<1><<<dim3((Mc + BM - 1)/BM, (HID + BN - 1)/BN), 256, 0, s2>>>(
            Mc, HID, EF, eattr + (size_t)e0 * EF, EF,
            msg_W1 + (size_t)(2 * NF) * HID, HID, nullptr, ph1, HID, 1,
            pdst + e0, psrc + e0, pPa, pPb, HID);
        cudaEventRecord(evE[c], s2);

        // L2 on main: fp16 2-product
        cudaStreamWaitEvent(0, evE[c], 0);
        if (c >= 2) cudaStreamWaitEvent(0, evL3[c - 2], 0);
        tmma_k<0,2><<<dim3(5, MT_E), 256, TSMEM>>>(Mc, HID, HID,
            ph1, HID, w2H, w2L, 320, msg_b2, ph2, HID, 1, nullptr);
        cudaEventRecord(evL2[c], 0);

        // L3 on s3: fp16 2-product + scatter
        cudaStreamWaitEvent(s3, evL2[c], 0);
        tmma_k<2,2><<<dim3(2, MT_E), 256, TSMEM, s3>>>(Mc, MSGD, HID,
            ph2, HID, w3H, w3L, 320, msg_b3, pag, MSGD, 0, pdst + e0);
        cudaEventRecord(evL3[c], s3);
    }

    // node MLP (bf16 3-product)
    cudaStreamWaitEvent(0, evL3[NCHUNK - 1], 0);
    concat_k<<<(NN * 256 + 255) / 256, 256>>>(x, NN);
    tmma_k<0,3><<<dim3(5, MT_N), 256, TSMEM>>>(NN, HID, NF + MSGD, pu, NF + MSGD,
        n1H, n1L, 256, node_b1, pn1, HID, 1, nullptr);
    tmma_k<0,3><<<dim3(5, MT_N), 256, TSMEM>>>(NN, HID, HID, pn1, HID,
        n2H, n2L, 320, node_b2, pn2, HID, 1, nullptr);
    tmma_k<0,3><<<dim3(2, MT_N), 256, TSMEM>>>(NN, NHID, HID, pn2, HID,
        n3H, n3L, 320, node_b3, phn, NHID, 0, nullptr);

    pool_k<<<(NN * NHID + 255) / 256, 256>>>(phn, NN);
    gmlp_k<<<NGRAPH, NHID>>>(glob_W1, glob_b1, glob_W2, glob_b2,
                             glob_W3, glob_b3, out);
}